// round 2
// baseline (speedup 1.0000x reference)
#include <cuda_runtime.h>
#include <math.h>

#define PI2F 6.28318530717958647692f

// ---------------- scratch (device globals; no allocation) ----------------
static __device__ float  g_conv[16*128*4096];      // conv2+BN+ReLU output
static __device__ float2 g_f   [16*128*4096];      // fft2 spectrum (later overwritten by g*f)
static __device__ float  g_norm[16*128];           // per-(b,c) spectral L2 norm
static __device__ float2 g_attn[16*8*256];         // softmaxed attention (b,h,16,16)
static __device__ float2 g_outf[16*128*4096];      // attention-applied spectrum / ifft scratch

// 16-pt inverse twiddles e^{+2*pi*i*t/16}
__constant__ float2 c_tw16[16] = {
  { 1.00000000f,  0.00000000f}, { 0.92387953f,  0.38268343f},
  { 0.70710678f,  0.70710678f}, { 0.38268343f,  0.92387953f},
  { 0.00000000f,  1.00000000f}, {-0.38268343f,  0.92387953f},
  {-0.70710678f,  0.70710678f}, {-0.92387953f,  0.38268343f},
  {-1.00000000f,  0.00000000f}, {-0.92387953f, -0.38268343f},
  {-0.70710678f, -0.70710678f}, {-0.38268343f, -0.92387953f},
  { 0.00000000f, -1.00000000f}, { 0.38268343f, -0.92387953f},
  { 0.70710678f, -0.70710678f}, { 0.92387953f, -0.38268343f}
};

// ---------------- complex helpers ----------------
struct cpx { float x, y; };
__device__ __forceinline__ cpx mk(float a, float b){ cpx r; r.x=a; r.y=b; return r; }
__device__ __forceinline__ cpx cadd(cpx a, cpx b){ return mk(a.x+b.x, a.y+b.y); }
__device__ __forceinline__ cpx csub(cpx a, cpx b){ return mk(a.x-b.x, a.y-b.y); }
__device__ __forceinline__ cpx cmul(cpx a, cpx b){ return mk(a.x*b.x - a.y*b.y, a.x*b.y + a.y*b.x); }

template<int S>
__device__ __forceinline__ cpx mulJ(cpx a){            // multiply by S*i
  return (S < 0) ? mk(a.y, -a.x) : mk(-a.y, a.x);
}

// e^{S * 2*pi*i * t / N}, N power of two
template<int S>
__device__ __forceinline__ cpx tw(int t, int N){
  t &= (N - 1);
  if (t > (N >> 1)) t -= N;
  float a = ((S < 0) ? -PI2F : PI2F) * (float)t / (float)N;
  float s, c;
  __sincosf(a, &s, &c);
  return mk(c, s);
}

template<int S>
__device__ __forceinline__ void dft8(cpx v[8]){
  const float r = 0.70710678118654752440f;
  cpx a0=cadd(v[0],v[4]), a1=csub(v[0],v[4]);
  cpx a2=cadd(v[2],v[6]), a3=csub(v[2],v[6]);
  cpx a4=cadd(v[1],v[5]), a5=csub(v[1],v[5]);
  cpx a6=cadd(v[3],v[7]), a7=csub(v[3],v[7]);
  cpx j3 = mulJ<S>(a3);
  cpx E0=cadd(a0,a2), E2=csub(a0,a2), E1=cadd(a1,j3), E3=csub(a1,j3);
  cpx j7 = mulJ<S>(a7);
  cpx O0=cadd(a4,a6), O2=csub(a4,a6), O1=cadd(a5,j7), O3=csub(a5,j7);
  cpx w1 = mk(r, (S<0)? -r : r);
  cpx w3 = mk(-r, (S<0)? -r : r);
  cpx t1 = cmul(O1, w1);
  cpx t2 = mulJ<S>(O2);
  cpx t3 = cmul(O3, w3);
  v[0]=cadd(E0,O0); v[4]=csub(E0,O0);
  v[1]=cadd(E1,t1); v[5]=csub(E1,t1);
  v[2]=cadd(E2,t2); v[6]=csub(E2,t2);
  v[3]=cadd(E3,t3); v[7]=csub(E3,t3);
}

// 64-pt DFT on elements br[i*stride], bi[i*stride], i=0..63, done by the
// 8 threads with lane id l (0..7) of one group. Natural order in and out.
// All threads of the block must call this (uniform); __syncthreads inside.
template<int S>
__device__ void fft64(float* br, float* bi, int stride, int l){
  cpx v[8];
  #pragma unroll
  for (int j=0;j<8;j++){ int id=(l+8*j)*stride; v[j]=mk(br[id], bi[id]); }
  dft8<S>(v);
  #pragma unroll
  for (int k=1;k<8;k++) v[k] = cmul(v[k], tw<S>(l*k, 64));
  __syncthreads();
  #pragma unroll
  for (int k=0;k<8;k++){ int id=(l*8+k)*stride; br[id]=v[k].x; bi[id]=v[k].y; }
  __syncthreads();
  #pragma unroll
  for (int j=0;j<8;j++){ int id=(j*8+l)*stride; v[j]=mk(br[id], bi[id]); }
  dft8<S>(v);
  #pragma unroll
  for (int k=0;k<8;k++){ int id=(k*8+l)*stride; br[id]=v[k].x; bi[id]=v[k].y; }
  __syncthreads();
}

// ---------------- K1: dilated 3x3 conv (d=3, pad=3) 256->128 + BN + ReLU ----
__global__ void __launch_bounds__(256) k_conv(const float* __restrict__ x,
                                              const float* __restrict__ w,
                                              const float* __restrict__ cb,
                                              const float* __restrict__ bsc,
                                              const float* __restrict__ bbi)
{
  __shared__ float s_in[8][22][24];
  __shared__ __align__(16) float s_w[2304];   // [jt=8*9][oc=32]
  int b = blockIdx.z;
  int ocBase = blockIdx.y * 32;
  int tileY = blockIdx.x >> 2, tileX = blockIdx.x & 3;
  int h0 = tileY*16, w0 = tileX*16;
  int tid = threadIdx.x;
  int og   = tid & 7;          // 8 groups of 4 output channels
  int colg = (tid>>3) & 1;     // 2 groups of 8 columns
  int ty   = tid >> 4;         // 16 rows

  float acc[4][8];
  #pragma unroll
  for (int o=0;o<4;o++)
    #pragma unroll
    for (int i=0;i<8;i++) acc[o][i]=0.f;

  for (int icb=0; icb<256; icb+=8){
    for (int idx=tid; idx<8*22*22; idx+=256){
      int j = idx / 484;
      int rm = idx - j*484;
      int r = rm / 22;
      int c = rm - r*22;
      int ih = h0 + r - 3, iw = w0 + c - 3;
      float v = 0.f;
      if (ih>=0 && ih<64 && iw>=0 && iw<64)
        v = x[(((b*256 + icb + j)*64) + ih)*64 + iw];
      s_in[j][r][c] = v;
    }
    for (int idx=tid; idx<2304; idx+=256){
      int o = idx & 31;
      int jt = idx >> 5;   // j*9 + tap
      s_w[jt*32 + o] = w[((ocBase + o)*256 + icb + (jt/9))*9 + (jt%9)];
    }
    __syncthreads();
    #pragma unroll
    for (int j=0;j<8;j++){
      #pragma unroll
      for (int dy=0;dy<3;dy++){
        float buf[14];
        const float* rp = &s_in[j][ty + dy*3][colg*8];
        #pragma unroll
        for (int c=0;c<14;c++) buf[c] = rp[c];
        #pragma unroll
        for (int dx=0;dx<3;dx++){
          const float4 wv = *(const float4*)&s_w[(j*9 + dy*3 + dx)*32 + og*4];
          #pragma unroll
          for (int i=0;i<8;i++){
            float v = buf[i + dx*3];
            acc[0][i] = fmaf(v, wv.x, acc[0][i]);
            acc[1][i] = fmaf(v, wv.y, acc[1][i]);
            acc[2][i] = fmaf(v, wv.z, acc[2][i]);
            acc[3][i] = fmaf(v, wv.w, acc[3][i]);
          }
        }
      }
    }
    __syncthreads();
  }
  #pragma unroll
  for (int o=0;o<4;o++){
    int oc = ocBase + og*4 + o;
    float sc = bsc[oc], bi2 = bbi[oc], b0 = cb[oc];
    #pragma unroll
    for (int i=0;i<8;i++){
      float v = (acc[o][i] + b0)*sc + bi2;
      g_conv[((b*128 + oc)*64 + h0+ty)*64 + (w0 + colg*8 + i)] = fmaxf(v, 0.f);
    }
  }
}

// ---------------- K2: forward fft2 over (h,w) + spectral row norms ----------
__global__ void __launch_bounds__(512) k_fft2(){
  __shared__ float sr[64][68], si[64][68];
  __shared__ float s_sum;
  int bc = blockIdx.x;
  int tid = threadIdx.x;
  if (tid==0) s_sum = 0.f;
  const float* src = &g_conv[bc*4096];
  for (int idx=tid; idx<4096; idx+=512){
    sr[idx>>6][idx&63] = src[idx];
    si[idx>>6][idx&63] = 0.f;
  }
  __syncthreads();
  int g = tid>>3, l = tid&7;
  fft64<-1>(&sr[0][g], &si[0][g], 68, l);  // over h (columns)
  fft64<-1>(&sr[g][0], &si[g][0], 1,  l);  // over w (rows)
  float part = 0.f;
  for (int idx=tid; idx<4096; idx+=512){
    float a = sr[idx>>6][idx&63], b2 = si[idx>>6][idx&63];
    g_f[bc*4096 + idx] = make_float2(a, b2);
    part += a*a + b2*b2;
  }
  #pragma unroll
  for (int s=16;s;s>>=1) part += __shfl_xor_sync(0xffffffffu, part, s);
  if ((tid&31)==0) atomicAdd(&s_sum, part);
  __syncthreads();
  if (tid==0) g_norm[bc] = sqrtf(s_sum);
}

// ---------------- K3: gram matrix + dual softmax ----------------
__global__ void __launch_bounds__(256) k_gram(const float* __restrict__ temp){
  __shared__ float2 sQ[16][129];
  int bh = blockIdx.x;
  int tid = threadIdx.x;
  int i = tid >> 4, jj = tid & 15;
  float ax=0.f, ay=0.f;
  for (int ch=0; ch<4096; ch+=128){
    for (int idx=tid; idx<2048; idx+=256)
      sQ[idx>>7][idx&127] = g_f[(bh*16 + (idx>>7))*4096 + ch + (idx&127)];
    __syncthreads();
    #pragma unroll 4
    for (int n=0;n<128;n++){
      float2 a = sQ[i][n], b = sQ[jj][n];
      ax = fmaf(a.x, b.x, ax); ax = fmaf(-a.y, b.y, ax);
      ay = fmaf(a.x, b.y, ay); ay = fmaf(a.y, b.x, ay);
    }
    __syncthreads();
  }
  float ni = fmaxf(g_norm[bh*16 + i],  1e-12f);
  float nj = fmaxf(g_norm[bh*16 + jj], 1e-12f);
  float sc = temp[bh & 7] / (ni*nj);
  float gr = ax*sc, gi = ay*sc;
  // dual softmax over jj (16-lane aligned groups)
  float mr = gr, mi = gi;
  #pragma unroll
  for (int m=8;m;m>>=1){
    mr = fmaxf(mr, __shfl_xor_sync(0xffffffffu, mr, m));
    mi = fmaxf(mi, __shfl_xor_sync(0xffffffffu, mi, m));
  }
  float er = __expf(gr - mr), ei = __expf(gi - mi);
  float srn = er, sin_ = ei;
  #pragma unroll
  for (int m=8;m;m>>=1){
    srn  += __shfl_xor_sync(0xffffffffu, srn, m);
    sin_ += __shfl_xor_sync(0xffffffffu, sin_, m);
  }
  g_attn[bh*256 + i*16 + jj] = make_float2(er/srn, ei/sin_);
}

// ---------------- K4: apply attention: out[i][n] = sum_j A[i][j] f[j][n] ----
__global__ void __launch_bounds__(512) k_apply(){
  __shared__ float2 sF[16][257];
  __shared__ float2 sA[256];
  int bh = blockIdx.x;
  int tid = threadIdx.x;
  if (tid < 256) sA[tid] = g_attn[bh*256 + tid];
  int nl = tid & 255;
  int ih = (tid >> 8) * 8;   // 0 or 8
  for (int ch=0; ch<4096; ch+=256){
    #pragma unroll
    for (int k=0;k<8;k++){
      int idx = tid + k*512;
      sF[idx>>8][idx&255] = g_f[(bh*16 + (idx>>8))*4096 + ch + (idx&255)];
    }
    __syncthreads();
    float2 acc[8];
    #pragma unroll
    for (int q=0;q<8;q++) acc[q] = make_float2(0.f, 0.f);
    #pragma unroll
    for (int j=0;j<16;j++){
      float2 fv = sF[j][nl];
      #pragma unroll
      for (int q=0;q<8;q++){
        float2 a = sA[(ih+q)*16 + j];
        acc[q].x = fmaf(a.x, fv.x, acc[q].x); acc[q].x = fmaf(-a.y, fv.y, acc[q].x);
        acc[q].y = fmaf(a.x, fv.y, acc[q].y); acc[q].y = fmaf(a.y, fv.x, acc[q].y);
      }
    }
    #pragma unroll
    for (int q=0;q<8;q++)
      g_outf[(bh*16 + ih + q)*4096 + ch + nl] = acc[q];
    __syncthreads();
  }
}

// ---------------- K5: in-place 4096-pt IFFT per row (no 1/N scale) ----------
__global__ void __launch_bounds__(512) k_ifft4096(){
  __shared__ float sr[64][68], si[64][68];
  int row = blockIdx.x;
  int tid = threadIdx.x;
  float2* base = &g_outf[row*4096];
  for (int idx=tid; idx<4096; idx+=512){
    float2 v = base[idx];
    sr[idx>>6][idx&63] = v.x;   // [k2][k1], k = k1 + 64*k2
    si[idx>>6][idx&63] = v.y;
  }
  __syncthreads();
  int g = tid>>3, l = tid&7;
  fft64<1>(&sr[0][g], &si[0][g], 68, l);    // IFFT over k2 -> [n2][k1]
  // inner twiddle e^{+2*pi*i*n2*k1/4096}
  for (int idx=tid; idx<4096; idx+=512){
    int n2 = idx>>6, k1 = idx&63;
    cpx t = tw<1>(n2*k1, 4096);
    cpx v = mk(sr[n2][k1], si[n2][k1]);
    v = cmul(v, t);
    sr[n2][k1] = v.x; si[n2][k1] = v.y;
  }
  __syncthreads();
  fft64<1>(&sr[g][0], &si[g][0], 1, l);     // IFFT over k1 -> [n2][n1]
  // out[n2 + 64*n1] = t[n2][n1]  (transposed read)
  for (int idx=tid; idx<4096; idx+=512)
    base[idx] = make_float2(sr[idx&63][idx>>6], si[idx&63][idx>>6]);
}

// ---------------- K6: 16-pt IDFT over cp + abs + residual (channels 0..127) -
__global__ void __launch_bounds__(256) k_ifft16(const float* __restrict__ x,
                                                float* __restrict__ out){
  int t = blockIdx.x*256 + threadIdx.x;     // 524288 threads
  int bh = t >> 12;
  int n  = t & 4095;
  int b  = bh >> 3;
  int h  = bh & 7;
  float2 v[16];
  #pragma unroll
  for (int i=0;i<16;i++) v[i] = g_outf[(bh*16 + i)*4096 + n];
  #pragma unroll
  for (int ip=0; ip<16; ip++){
    float ax = 0.f, ay = 0.f;
    #pragma unroll
    for (int i=0;i<16;i++){
      float2 w2 = c_tw16[(i*ip) & 15];
      ax = fmaf(v[i].x, w2.x, ax); ax = fmaf(-v[i].y, w2.y, ax);
      ay = fmaf(v[i].x, w2.y, ay); ay = fmaf( v[i].y, w2.x, ay);
    }
    int c = h*16 + ip;
    int oi = (b*256 + c)*4096 + n;
    out[oi] = sqrtf(ax*ax + ay*ay) * (1.f/65536.f) + x[oi];
  }
}

// ---------------- K7: gating MLP, scales g_f in place ----------------
__global__ void __launch_bounds__(256) k_gate(const float* __restrict__ w1,
                                              const float* __restrict__ w1b,
                                              const float* __restrict__ bnws,
                                              const float* __restrict__ bnwb,
                                              const float* __restrict__ w2,
                                              const float* __restrict__ w2b)
{
  __shared__ float s_w1[8*128];
  __shared__ float s_w2[128*8];
  __shared__ float s_tb[8], s_ta[8];
  __shared__ float s_b2[128];
  int tid = threadIdx.x;
  for (int idx=tid; idx<1024; idx+=256){ s_w1[idx] = w1[idx]; s_w2[idx] = w2[idx]; }
  if (tid < 8){ float a = bnws[tid]; s_ta[tid] = a; s_tb[tid] = w1b[tid]*a + bnwb[tid]; }
  if (tid < 128) s_b2[tid] = w2b[tid];
  __syncthreads();

  int t = blockIdx.x*256 + tid;      // 65536 threads: (b, pixel)
  int b = t >> 12;
  int p = t & 4095;
  float2* fp = &g_f[(size_t)b*128*4096 + p];

  float acc[8];
  #pragma unroll
  for (int q=0;q<8;q++) acc[q] = 0.f;
  for (int c=0;c<128;c++){
    float r = fp[(size_t)c*4096].x;
    #pragma unroll
    for (int q=0;q<8;q++) acc[q] = fmaf(s_w1[q*128 + c], r, acc[q]);
  }
  float tq[8];
  #pragma unroll
  for (int q=0;q<8;q++) tq[q] = fmaxf(fmaf(acc[q], s_ta[q], s_tb[q]), 0.f);

  for (int c=0;c<128;c++){
    float s = s_b2[c];
    #pragma unroll
    for (int q=0;q<8;q++) s = fmaf(s_w2[c*8 + q], tq[q], s);
    float gate = 1.f / (1.f + __expf(-s));
    float2 fv = fp[(size_t)c*4096];
    fp[(size_t)c*4096] = make_float2(fv.x*gate, fv.y*gate);
  }
}

// ---------------- K8: spatial inverse fft2 of g*f + abs + residual ----------
__global__ void __launch_bounds__(512) k_ifft2sp(const float* __restrict__ x,
                                                 float* __restrict__ out){
  __shared__ float sr[64][68], si[64][68];
  int bc = blockIdx.x;                 // b*128 + c
  int tid = threadIdx.x;
  const float2* base = &g_f[(size_t)bc*4096];
  for (int idx=tid; idx<4096; idx+=512){
    float2 v = base[idx];
    sr[idx>>6][idx&63] = v.x;
    si[idx>>6][idx&63] = v.y;
  }
  __syncthreads();
  int g = tid>>3, l = tid&7;
  fft64<1>(&sr[0][g], &si[0][g], 68, l);
  fft64<1>(&sr[g][0], &si[g][0], 1,  l);
  int b = bc >> 7, c = bc & 127;
  const float* xb = &x[((size_t)b*256 + 128 + c)*4096];
  float* ob = &out[((size_t)b*256 + 128 + c)*4096];
  for (int idx=tid; idx<4096; idx+=512){
    float a = sr[idx>>6][idx&63], b2 = si[idx>>6][idx&63];
    ob[idx] = sqrtf(a*a + b2*b2) * (1.f/4096.f) + xb[idx];
  }
}

// ---------------- launch ----------------
extern "C" void kernel_launch(void* const* d_in, const int* in_sizes, int n_in,
                              void* d_out, int out_size) {
  (void)in_sizes; (void)n_in; (void)out_size;
  const float* x     = (const float*)d_in[0];
  const float* c2w   = (const float*)d_in[1];
  const float* c2b   = (const float*)d_in[2];
  const float* bn2s  = (const float*)d_in[3];
  const float* bn2b  = (const float*)d_in[4];
  const float* temp  = (const float*)d_in[5];
  const float* w1w   = (const float*)d_in[6];
  const float* w1b   = (const float*)d_in[7];
  const float* bnws  = (const float*)d_in[8];
  const float* bnwb  = (const float*)d_in[9];
  const float* w2w   = (const float*)d_in[10];
  const float* w2b   = (const float*)d_in[11];
  float* out = (float*)d_out;

  k_conv<<<dim3(16,4,16), 256>>>(x, c2w, c2b, bn2s, bn2b);
  k_fft2<<<2048, 512>>>();
  k_gram<<<128, 256>>>(temp);
  k_apply<<<128, 512>>>();
  k_ifft4096<<<2048, 512>>>();
  k_ifft16<<<2048, 256>>>(x, out);
  k_gate<<<256, 256>>>(w1w, w1b, bnws, bnwb, w2w, w2b);
  k_ifft2sp<<<2048, 512>>>(x, out);
}

// round 4
// speedup vs baseline: 1.5272x; 1.5272x over previous
#include <cuda_runtime.h>
#include <cuda_bf16.h>
#include <math.h>
#include <stdint.h>

#define PI2F 6.28318530717958647692f

// ---------------- scratch (device globals; no allocation) ----------------
static __device__ float  g_conv[16*128*4096];      // conv2+BN+ReLU output
static __device__ float2 g_f   [16*128*4096];      // fft2 spectrum (later overwritten by g*f)
static __device__ float  g_norm[16*128];           // per-(b,c) spectral L2 norm
static __device__ float2 g_attn[16*8*256];         // softmaxed attention (b,h,16,16)
static __device__ float2 g_outf[16*128*4096];      // attention-applied spectrum / ifft scratch
static __device__ uint32_t g_xhi[16*128*4096];     // X split: hi bf16 pair (ic,ic+1)
static __device__ uint32_t g_xlo[16*128*4096];     // X split: lo bf16 pair
static __device__ uint32_t g_wsplit[36*8192];      // weight chunks, pre-swizzled hi/lo planes

// 16-pt inverse twiddles e^{+2*pi*i*t/16}
__constant__ float2 c_tw16[16] = {
  { 1.00000000f,  0.00000000f}, { 0.92387953f,  0.38268343f},
  { 0.70710678f,  0.70710678f}, { 0.38268343f,  0.92387953f},
  { 0.00000000f,  1.00000000f}, {-0.38268343f,  0.92387953f},
  {-0.70710678f,  0.70710678f}, {-0.92387953f,  0.38268343f},
  {-1.00000000f,  0.00000000f}, {-0.92387953f, -0.38268343f},
  {-0.70710678f, -0.70710678f}, {-0.38268343f, -0.92387953f},
  { 0.00000000f, -1.00000000f}, { 0.38268343f, -0.92387953f},
  { 0.70710678f, -0.70710678f}, { 0.92387953f, -0.38268343f}
};

// ================= helpers =================
__device__ __forceinline__ uint32_t smem_u32(const void* p){
  uint32_t a;
  asm("{ .reg .u64 t; cvta.to.shared.u64 t, %1; cvt.u32.u64 %0, t; }" : "=r"(a) : "l"(p));
  return a;
}
__device__ __forceinline__ uint32_t pack_hi(float v0, float v1, uint32_t& lo){
  __nv_bfloat16 a0 = __float2bfloat16_rn(v0), a1 = __float2bfloat16_rn(v1);
  __nv_bfloat16 l0 = __float2bfloat16_rn(v0 - __bfloat162float(a0));
  __nv_bfloat16 l1 = __float2bfloat16_rn(v1 - __bfloat162float(a1));
  lo = (uint32_t)__bfloat16_as_ushort(l0) | ((uint32_t)__bfloat16_as_ushort(l1) << 16);
  return (uint32_t)__bfloat16_as_ushort(a0) | ((uint32_t)__bfloat16_as_ushort(a1) << 16);
}
__device__ __forceinline__ void ldmx4(uint32_t* d, uint32_t addr){
  asm volatile("ldmatrix.sync.aligned.m8n8.x4.shared.b16 {%0,%1,%2,%3}, [%4];"
               : "=r"(d[0]), "=r"(d[1]), "=r"(d[2]), "=r"(d[3]) : "r"(addr));
}
__device__ __forceinline__ void mma16816(float* d, const uint32_t* a, const uint32_t* b){
  asm volatile(
    "mma.sync.aligned.m16n8k16.row.col.f32.bf16.bf16.f32 "
    "{%0,%1,%2,%3}, {%4,%5,%6,%7}, {%8,%9}, {%0,%1,%2,%3};"
    : "+f"(d[0]), "+f"(d[1]), "+f"(d[2]), "+f"(d[3])
    : "r"(a[0]), "r"(a[1]), "r"(a[2]), "r"(a[3]), "r"(b[0]), "r"(b[1]));
}

// ---------------- K0a: split X into bf16 hi/lo ic-pairs ----------------
__global__ void __launch_bounds__(256) k_xprep(const float* __restrict__ X){
  int idx = blockIdx.x*256 + threadIdx.x;     // 16*128*4096
  int b   = idx >> 19;
  int icp = (idx >> 12) & 127;
  int hw  = idx & 4095;
  const float* p = &X[(((size_t)b*256 + 2*icp)*4096) + hw];
  uint32_t lo, hi = pack_hi(p[0], p[4096], lo);
  g_xhi[idx] = hi; g_xlo[idx] = lo;
}

// ---------------- K0b: split + pre-swizzle weights per chunk ----------------
__global__ void __launch_bounds__(256) k_wprep(const float* __restrict__ W){
  int idx = blockIdx.x*256 + threadIdx.x;     // 36*4096 = 147456
  int chunk = idx >> 12;
  int rem = idx & 4095;
  int oc = rem >> 5, icp = rem & 31;
  int tap = chunk >> 2, icb = (chunk & 3) << 6;
  int ic = icb + 2*icp;
  float v0 = W[(size_t)(oc*256 + ic)*9 + tap];
  float v1 = W[(size_t)(oc*256 + ic + 1)*9 + tap];
  uint32_t lo, hi = pack_hi(v0, v1, lo);
  uint32_t off = ((uint32_t)(oc*128 + icp*4)) ^ (((uint32_t)(oc & 7)) << 4);
  g_wsplit[(chunk*32768u + off) >> 2]          = hi;
  g_wsplit[(chunk*32768u + 16384u + off) >> 2] = lo;
}

// ---------------- K1: conv as HMMA implicit GEMM (bf16 2-split) ----------
// D[px,oc] = sum_{tap,ic} X[b,ic,h+dy,w+dx] * W[oc,ic,tap]
// CTA: M=128 px (2 image rows) x N=128 oc, K=2304 in 36 chunks of 64.
__global__ void __launch_bounds__(256) k_conv_mma(const float* __restrict__ cbp,
                                                  const float* __restrict__ bsc,
                                                  const float* __restrict__ bbi)
{
  extern __shared__ __align__(128) char sm[];   // 64KB: Ahi,Alo,Bhi,Blo @ 16KB each
  __shared__ float s_prm[384];
  const int tid = threadIdx.x;
  const int wid = tid >> 5, lane = tid & 31;
  const int wm = wid & 3, wn = wid >> 2;
  const int b    = blockIdx.x >> 5;
  const int tile = blockIdx.x & 31;
  const int h0   = tile * 2;

  if (tid < 128){
    s_prm[tid]       = cbp[tid];
    s_prm[128 + tid] = bsc[tid];
    s_prm[256 + tid] = bbi[tid];
  }

  const uint32_t smb = smem_u32(sm);
  const int m = lane >> 3, r = lane & 7;

  // ldmatrix lane row/xor precompute
  int rowA[2], xrA[2];
  #pragma unroll
  for (int mt=0; mt<2; ++mt){
    rowA[mt] = wm*32 + mt*16 + (m & 1)*8 + r;
    xrA[mt]  = (rowA[mt] & 7) << 4;
  }
  const int colAhalf = (m >> 1) * 16;
  int rowB[4], xrB[4];
  #pragma unroll
  for (int ntp=0; ntp<4; ++ntp){
    rowB[ntp] = wn*64 + ntp*16 + (m >> 1)*8 + r;
    xrB[ntp]  = (rowB[ntp] & 7) << 4;
  }
  const int colBhalf = (m & 1) * 16;

  float acc[2][8][4];
  #pragma unroll
  for (int i=0;i<2;i++)
    #pragma unroll
    for (int j=0;j<8;j++)
      #pragma unroll
      for (int q=0;q<4;q++) acc[i][j][q] = 0.f;

  __syncthreads();

  for (int n = 0; n < 36; ++n){
    const int tap = n >> 2;
    const int dy = (tap / 3) * 3 - 3, dx = (tap % 3) * 3 - 3;
    const int icpg0 = (n & 3) * 32;

    // ---- A fill: 128 px x 32 ic-pairs (hi+lo planes) ----
    #pragma unroll 4
    for (int it = 0; it < 16; ++it){
      int idx = it * 256 + tid;
      int icp = idx >> 7;          // 0..31
      int px  = idx & 127;
      int hh = h0 + (px >> 6) + dy;
      int ww = (px & 63) + dx;
      uint32_t hi = 0, lo = 0;
      if (hh >= 0 && hh < 64 && ww >= 0 && ww < 64){
        int gi = ((b*128 + icpg0 + icp) << 12) + hh*64 + ww;
        hi = g_xhi[gi]; lo = g_xlo[gi];
      }
      uint32_t off = ((uint32_t)(px*128 + icp*4)) ^ (((uint32_t)(px & 7)) << 4);
      *(uint32_t*)(sm + off)          = hi;
      *(uint32_t*)(sm + 16384 + off)  = lo;
    }
    // ---- B fill: straight 32KB copy of pre-swizzled hi+lo planes ----
    {
      const uint4* wsrc = (const uint4*)&g_wsplit[n * 8192];
      uint4* bdst = (uint4*)(sm + 32768);
      #pragma unroll
      for (int j = 0; j < 8; ++j)
        bdst[tid + j*256] = wsrc[tid + j*256];
    }
    __syncthreads();

    // ---- MMA: warp tile 32(M) x 64(N), K=64 ----
    #pragma unroll
    for (int kk = 0; kk < 4; ++kk){
      uint32_t ah[2][4], al[2][4];
      const int colA = kk*32 + colAhalf;
      #pragma unroll
      for (int mt=0; mt<2; ++mt){
        uint32_t aaddr = smb + rowA[mt]*128 + (colA ^ xrA[mt]);
        ldmx4(ah[mt], aaddr);
        ldmx4(al[mt], aaddr + 16384);
      }
      const int colB = kk*32 + colBhalf;
      #pragma unroll
      for (int ntp=0; ntp<4; ++ntp){
        uint32_t bh[4], bl[4];
        uint32_t baddr = smb + 32768 + rowB[ntp]*128 + (colB ^ xrB[ntp]);
        ldmx4(bh, baddr);
        ldmx4(bl, baddr + 16384);
        #pragma unroll
        for (int mt=0; mt<2; ++mt){
          #pragma unroll
          for (int hf=0; hf<2; ++hf){
            float* d = acc[mt][ntp*2 + hf];
            mma16816(d, ah[mt], bh + hf*2);
            mma16816(d, ah[mt], bl + hf*2);
            mma16816(d, al[mt], bh + hf*2);
          }
        }
      }
    }
    __syncthreads();
  }

  // ---- epilogue: BN + ReLU + store ----
  const int g2 = lane >> 2, tig = lane & 3;
  float* outb = &g_conv[(size_t)b*128*4096 + h0*64];
  #pragma unroll
  for (int mt=0; mt<2; ++mt){
    int px0 = wm*32 + mt*16 + g2;
    #pragma unroll
    for (int nt=0; nt<8; ++nt){
      int oc0 = wn*64 + nt*8 + 2*tig;
      #pragma unroll
      for (int q=0; q<4; ++q){
        int px = px0 + (q >> 1)*8;
        int oc = oc0 + (q & 1);
        float v = (acc[mt][nt][q] + s_prm[oc]) * s_prm[128+oc] + s_prm[256+oc];
        outb[(size_t)oc*4096 + px] = fmaxf(v, 0.f);
      }
    }
  }
}

// ---------------- complex helpers ----------------
struct cpx { float x, y; };
__device__ __forceinline__ cpx mk(float a, float b){ cpx r; r.x=a; r.y=b; return r; }
__device__ __forceinline__ cpx cadd(cpx a, cpx b){ return mk(a.x+b.x, a.y+b.y); }
__device__ __forceinline__ cpx csub(cpx a, cpx b){ return mk(a.x-b.x, a.y-b.y); }
__device__ __forceinline__ cpx cmul(cpx a, cpx b){ return mk(a.x*b.x - a.y*b.y, a.x*b.y + a.y*b.x); }

template<int S>
__device__ __forceinline__ cpx mulJ(cpx a){
  return (S < 0) ? mk(a.y, -a.x) : mk(-a.y, a.x);
}
template<int S>
__device__ __forceinline__ cpx tw(int t, int N){
  t &= (N - 1);
  if (t > (N >> 1)) t -= N;
  float a = ((S < 0) ? -PI2F : PI2F) * (float)t / (float)N;
  float s, c;
  __sincosf(a, &s, &c);
  return mk(c, s);
}
template<int S>
__device__ __forceinline__ void dft8(cpx v[8]){
  const float r = 0.70710678118654752440f;
  cpx a0=cadd(v[0],v[4]), a1=csub(v[0],v[4]);
  cpx a2=cadd(v[2],v[6]), a3=csub(v[2],v[6]);
  cpx a4=cadd(v[1],v[5]), a5=csub(v[1],v[5]);
  cpx a6=cadd(v[3],v[7]), a7=csub(v[3],v[7]);
  cpx j3 = mulJ<S>(a3);
  cpx E0=cadd(a0,a2), E2=csub(a0,a2), E1=cadd(a1,j3), E3=csub(a1,j3);
  cpx j7 = mulJ<S>(a7);
  cpx O0=cadd(a4,a6), O2=csub(a4,a6), O1=cadd(a5,j7), O3=csub(a5,j7);
  cpx w1 = mk(r, (S<0)? -r : r);
  cpx w3 = mk(-r, (S<0)? -r : r);
  cpx t1 = cmul(O1, w1);
  cpx t2 = mulJ<S>(O2);
  cpx t3 = cmul(O3, w3);
  v[0]=cadd(E0,O0); v[4]=csub(E0,O0);
  v[1]=cadd(E1,t1); v[5]=csub(E1,t1);
  v[2]=cadd(E2,t2); v[6]=csub(E2,t2);
  v[3]=cadd(E3,t3); v[7]=csub(E3,t3);
}
template<int S>
__device__ void fft64(float* br, float* bi, int stride, int l){
  cpx v[8];
  #pragma unroll
  for (int j=0;j<8;j++){ int id=(l+8*j)*stride; v[j]=mk(br[id], bi[id]); }
  dft8<S>(v);
  #pragma unroll
  for (int k=1;k<8;k++) v[k] = cmul(v[k], tw<S>(l*k, 64));
  __syncthreads();
  #pragma unroll
  for (int k=0;k<8;k++){ int id=(l*8+k)*stride; br[id]=v[k].x; bi[id]=v[k].y; }
  __syncthreads();
  #pragma unroll
  for (int j=0;j<8;j++){ int id=(j*8+l)*stride; v[j]=mk(br[id], bi[id]); }
  dft8<S>(v);
  #pragma unroll
  for (int k=0;k<8;k++){ int id=(k*8+l)*stride; br[id]=v[k].x; bi[id]=v[k].y; }
  __syncthreads();
}

// ---------------- K2: forward fft2 over (h,w) + spectral row norms ----------
__global__ void __launch_bounds__(512) k_fft2(){
  __shared__ float sr[64][68], si[64][68];
  __shared__ float s_sum;
  int bc = blockIdx.x;
  int tid = threadIdx.x;
  if (tid==0) s_sum = 0.f;
  const float* src = &g_conv[bc*4096];
  for (int idx=tid; idx<4096; idx+=512){
    sr[idx>>6][idx&63] = src[idx];
    si[idx>>6][idx&63] = 0.f;
  }
  __syncthreads();
  int g = tid>>3, l = tid&7;
  fft64<-1>(&sr[0][g], &si[0][g], 68, l);
  fft64<-1>(&sr[g][0], &si[g][0], 1,  l);
  float part = 0.f;
  for (int idx=tid; idx<4096; idx+=512){
    float a = sr[idx>>6][idx&63], b2 = si[idx>>6][idx&63];
    g_f[bc*4096 + idx] = make_float2(a, b2);
    part += a*a + b2*b2;
  }
  #pragma unroll
  for (int s=16;s;s>>=1) part += __shfl_xor_sync(0xffffffffu, part, s);
  if ((tid&31)==0) atomicAdd(&s_sum, part);
  __syncthreads();
  if (tid==0) g_norm[bc] = sqrtf(s_sum);
}

// ---------------- K3: gram matrix + dual softmax ----------------
__global__ void __launch_bounds__(256) k_gram(const float* __restrict__ temp){
  __shared__ float2 sQ[16][129];
  int bh = blockIdx.x;
  int tid = threadIdx.x;
  int i = tid >> 4, jj = tid & 15;
  float ax=0.f, ay=0.f;
  for (int ch=0; ch<4096; ch+=128){
    for (int idx=tid; idx<2048; idx+=256)
      sQ[idx>>7][idx&127] = g_f[(bh*16 + (idx>>7))*4096 + ch + (idx&127)];
    __syncthreads();
    #pragma unroll 4
    for (int n=0;n<128;n++){
      float2 a = sQ[i][n], b = sQ[jj][n];
      ax = fmaf(a.x, b.x, ax); ax = fmaf(-a.y, b.y, ax);
      ay = fmaf(a.x, b.y, ay); ay = fmaf(a.y, b.x, ay);
    }
    __syncthreads();
  }
  float ni = fmaxf(g_norm[bh*16 + i],  1e-12f);
  float nj = fmaxf(g_norm[bh*16 + jj], 1e-12f);
  float sc = temp[bh & 7] / (ni*nj);
  float gr = ax*sc, gi = ay*sc;
  float mr = gr, mi = gi;
  #pragma unroll
  for (int m2=8;m2;m2>>=1){
    mr = fmaxf(mr, __shfl_xor_sync(0xffffffffu, mr, m2));
    mi = fmaxf(mi, __shfl_xor_sync(0xffffffffu, mi, m2));
  }
  float er = __expf(gr - mr), ei = __expf(gi - mi);
  float srn = er, sin_ = ei;
  #pragma unroll
  for (int m2=8;m2;m2>>=1){
    srn  += __shfl_xor_sync(0xffffffffu, srn, m2);
    sin_ += __shfl_xor_sync(0xffffffffu, sin_, m2);
  }
  g_attn[bh*256 + i*16 + jj] = make_float2(er/srn, ei/sin_);
}

// ---------------- K4: apply attention ----------------
__global__ void __launch_bounds__(512) k_apply(){
  __shared__ float2 sF[16][257];
  __shared__ float2 sA[256];
  int bh = blockIdx.x;
  int tid = threadIdx.x;
  if (tid < 256) sA[tid] = g_attn[bh*256 + tid];
  int nl = tid & 255;
  int ih = (tid >> 8) * 8;
  for (int ch=0; ch<4096; ch+=256){
    #pragma unroll
    for (int k=0;k<8;k++){
      int idx = tid + k*512;
      sF[idx>>8][idx&255] = g_f[(bh*16 + (idx>>8))*4096 + ch + (idx&255)];
    }
    __syncthreads();
    float2 acc[8];
    #pragma unroll
    for (int q=0;q<8;q++) acc[q] = make_float2(0.f, 0.f);
    #pragma unroll
    for (int j=0;j<16;j++){
      float2 fv = sF[j][nl];
      #pragma unroll
      for (int q=0;q<8;q++){
        float2 a = sA[(ih+q)*16 + j];
        acc[q].x = fmaf(a.x, fv.x, acc[q].x); acc[q].x = fmaf(-a.y, fv.y, acc[q].x);
        acc[q].y = fmaf(a.x, fv.y, acc[q].y); acc[q].y = fmaf(a.y, fv.x, acc[q].y);
      }
    }
    #pragma unroll
    for (int q=0;q<8;q++)
      g_outf[(bh*16 + ih + q)*4096 + ch + nl] = acc[q];
    __syncthreads();
  }
}

// ---------------- K5: in-place 4096-pt IFFT per row ----------
__global__ void __launch_bounds__(512) k_ifft4096(){
  __shared__ float sr[64][68], si[64][68];
  int row = blockIdx.x;
  int tid = threadIdx.x;
  float2* base = &g_outf[row*4096];
  for (int idx=tid; idx<4096; idx+=512){
    float2 v = base[idx];
    sr[idx>>6][idx&63] = v.x;
    si[idx>>6][idx&63] = v.y;
  }
  __syncthreads();
  int g = tid>>3, l = tid&7;
  fft64<1>(&sr[0][g], &si[0][g], 68, l);
  for (int idx=tid; idx<4096; idx+=512){
    int n2 = idx>>6, k1 = idx&63;
    cpx t = tw<1>(n2*k1, 4096);
    cpx v = mk(sr[n2][k1], si[n2][k1]);
    v = cmul(v, t);
    sr[n2][k1] = v.x; si[n2][k1] = v.y;
  }
  __syncthreads();
  fft64<1>(&sr[g][0], &si[g][0], 1, l);
  for (int idx=tid; idx<4096; idx+=512)
    base[idx] = make_float2(sr[idx&63][idx>>6], si[idx&63][idx>>6]);
}

// ---------------- K6: 16-pt IDFT over cp + abs + residual ----------
__global__ void __launch_bounds__(256) k_ifft16(const float* __restrict__ x,
                                                float* __restrict__ out){
  int t = blockIdx.x*256 + threadIdx.x;
  int bh = t >> 12;
  int n  = t & 4095;
  int b  = bh >> 3;
  int h  = bh & 7;
  float2 v[16];
  #pragma unroll
  for (int i=0;i<16;i++) v[i] = g_outf[(bh*16 + i)*4096 + n];
  #pragma unroll
  for (int ip=0; ip<16; ip++){
    float ax = 0.f, ay = 0.f;
    #pragma unroll
    for (int i=0;i<16;i++){
      float2 w2 = c_tw16[(i*ip) & 15];
      ax = fmaf(v[i].x, w2.x, ax); ax = fmaf(-v[i].y, w2.y, ax);
      ay = fmaf(v[i].x, w2.y, ay); ay = fmaf( v[i].y, w2.x, ay);
    }
    int c = h*16 + ip;
    int oi = (b*256 + c)*4096 + n;
    out[oi] = sqrtf(ax*ax + ay*ay) * (1.f/65536.f) + x[oi];
  }
}

// ---------------- K7: gating MLP, scales g_f in place ----------------
__global__ void __launch_bounds__(256) k_gate(const float* __restrict__ w1,
                                              const float* __restrict__ w1b,
                                              const float* __restrict__ bnws,
                                              const float* __restrict__ bnwb,
                                              const float* __restrict__ w2,
                                              const float* __restrict__ w2b)
{
  __shared__ float s_w1[8*128];
  __shared__ float s_w2[128*8];
  __shared__ float s_tb[8], s_ta[8];
  __shared__ float s_b2[128];
  int tid = threadIdx.x;
  for (int idx=tid; idx<1024; idx+=256){ s_w1[idx] = w1[idx]; s_w2[idx] = w2[idx]; }
  if (tid < 8){ float a = bnws[tid]; s_ta[tid] = a; s_tb[tid] = w1b[tid]*a + bnwb[tid]; }
  if (tid < 128) s_b2[tid] = w2b[tid];
  __syncthreads();

  int t = blockIdx.x*256 + tid;
  int b = t >> 12;
  int p = t & 4095;
  float2* fp = &g_f[(size_t)b*128*4096 + p];

  float acc[8];
  #pragma unroll
  for (int q=0;q<8;q++) acc[q] = 0.f;
  for (int c=0;c<128;c++){
    float r = fp[(size_t)c*4096].x;
    #pragma unroll
    for (int q=0;q<8;q++) acc[q] = fmaf(s_w1[q*128 + c], r, acc[q]);
  }
  float tq[8];
  #pragma unroll
  for (int q=0;q<8;q++) tq[q] = fmaxf(fmaf(acc[q], s_ta[q], s_tb[q]), 0.f);

  for (int c=0;c<128;c++){
    float s = s_b2[c];
    #pragma unroll
    for (int q=0;q<8;q++) s = fmaf(s_w2[c*8 + q], tq[q], s);
    float gate = 1.f / (1.f + __expf(-s));
    float2 fv = fp[(size_t)c*4096];
    fp[(size_t)c*4096] = make_float2(fv.x*gate, fv.y*gate);
  }
}

// ---------------- K8: spatial inverse fft2 of g*f + abs + residual ----------
__global__ void __launch_bounds__(512) k_ifft2sp(const float* __restrict__ x,
                                                 float* __restrict__ out){
  __shared__ float sr[64][68], si[64][68];
  int bc = blockIdx.x;
  int tid = threadIdx.x;
  const float2* base = &g_f[(size_t)bc*4096];
  for (int idx=tid; idx<4096; idx+=512){
    float2 v = base[idx];
    sr[idx>>6][idx&63] = v.x;
    si[idx>>6][idx&63] = v.y;
  }
  __syncthreads();
  int g = tid>>3, l = tid&7;
  fft64<1>(&sr[0][g], &si[0][g], 68, l);
  fft64<1>(&sr[g][0], &si[g][0], 1,  l);
  int b = bc >> 7, c = bc & 127;
  const float* xb = &x[((size_t)b*256 + 128 + c)*4096];
  float* ob = &out[((size_t)b*256 + 128 + c)*4096];
  for (int idx=tid; idx<4096; idx+=512){
    float a = sr[idx>>6][idx&63], b2 = si[idx>>6][idx&63];
    ob[idx] = sqrtf(a*a + b2*b2) * (1.f/4096.f) + xb[idx];
  }
}

// ---------------- launch ----------------
extern "C" void kernel_launch(void* const* d_in, const int* in_sizes, int n_in,
                              void* d_out, int out_size) {
  (void)in_sizes; (void)n_in; (void)out_size;
  const float* x     = (const float*)d_in[0];
  const float* c2w   = (const float*)d_in[1];
  const float* c2b   = (const float*)d_in[2];
  const float* bn2s  = (const float*)d_in[3];
  const float* bn2b  = (const float*)d_in[4];
  const float* temp  = (const float*)d_in[5];
  const float* w1w   = (const float*)d_in[6];
  const float* w1b   = (const float*)d_in[7];
  const float* bnws  = (const float*)d_in[8];
  const float* bnwb  = (const float*)d_in[9];
  const float* w2w   = (const float*)d_in[10];
  const float* w2b   = (const float*)d_in[11];
  float* out = (float*)d_out;

  const int SMEM_CONV = 65536;
  cudaFuncSetAttribute(k_conv_mma, cudaFuncAttributeMaxDynamicSharedMemorySize, SMEM_CONV);

  k_xprep<<<32768, 256>>>(x);
  k_wprep<<<576, 256>>>(c2w);
  k_conv_mma<<<512, 256, SMEM_CONV>>>(c2b, bn2s, bn2b);
  k_fft2<<<2048, 512>>>();
  k_gram<<<128, 256>>>(temp);
  k_apply<<<128, 512>>>();
  k_ifft4096<<<2048, 512>>>();
  k_ifft16<<<2048, 256>>>(x, out);
  k_gate<<<256, 256>>>(w1w, w1b, bnws, bnwb, w2w, w2b);
  k_ifft2sp<<<2048, 512>>>(x, out);
}

// round 5
// speedup vs baseline: 1.8933x; 1.2397x over previous
#include <cuda_runtime.h>
#include <cuda_bf16.h>
#include <math.h>
#include <stdint.h>

#define PI2F 6.28318530717958647692f

// ---------------- scratch (device globals; no allocation) ----------------
static __device__ float  g_conv[16*128*4096];      // conv2+BN+ReLU output
static __device__ float2 g_f   [16*128*4096];      // fft2 spectrum (later overwritten by g*f)
static __device__ float  g_norm[16*128];           // per-(b,c) spectral L2 norm
static __device__ float2 g_attn[16*8*256];         // softmaxed attention (b,h,16,16)
static __device__ float2 g_outf[16*128*4096];      // attention-applied spectrum / ifft scratch
static __device__ uint32_t g_xhi[16*4096*128];     // X split hi, pixel-major: [b][hw][icp]
static __device__ uint32_t g_xlo[16*4096*128];     // X split lo, pixel-major
static __device__ uint32_t g_wsplit[36*8192];      // weight chunks, pre-swizzled hi/lo planes

// 16-pt inverse twiddles e^{+2*pi*i*t/16}
__constant__ float2 c_tw16[16] = {
  { 1.00000000f,  0.00000000f}, { 0.92387953f,  0.38268343f},
  { 0.70710678f,  0.70710678f}, { 0.38268343f,  0.92387953f},
  { 0.00000000f,  1.00000000f}, {-0.38268343f,  0.92387953f},
  {-0.70710678f,  0.70710678f}, {-0.92387953f,  0.38268343f},
  {-1.00000000f,  0.00000000f}, {-0.92387953f, -0.38268343f},
  {-0.70710678f, -0.70710678f}, {-0.38268343f, -0.92387953f},
  { 0.00000000f, -1.00000000f}, { 0.38268343f, -0.92387953f},
  { 0.70710678f, -0.70710678f}, { 0.92387953f, -0.38268343f}
};

// ================= helpers =================
__device__ __forceinline__ uint32_t smem_u32(const void* p){
  uint32_t a;
  asm("{ .reg .u64 t; cvta.to.shared.u64 t, %1; cvt.u32.u64 %0, t; }" : "=r"(a) : "l"(p));
  return a;
}
__device__ __forceinline__ uint32_t pack_hi(float v0, float v1, uint32_t& lo){
  __nv_bfloat16 a0 = __float2bfloat16_rn(v0), a1 = __float2bfloat16_rn(v1);
  __nv_bfloat16 l0 = __float2bfloat16_rn(v0 - __bfloat162float(a0));
  __nv_bfloat16 l1 = __float2bfloat16_rn(v1 - __bfloat162float(a1));
  lo = (uint32_t)__bfloat16_as_ushort(l0) | ((uint32_t)__bfloat16_as_ushort(l1) << 16);
  return (uint32_t)__bfloat16_as_ushort(a0) | ((uint32_t)__bfloat16_as_ushort(a1) << 16);
}
__device__ __forceinline__ void ldmx4(uint32_t* d, uint32_t addr){
  asm volatile("ldmatrix.sync.aligned.m8n8.x4.shared.b16 {%0,%1,%2,%3}, [%4];"
               : "=r"(d[0]), "=r"(d[1]), "=r"(d[2]), "=r"(d[3]) : "r"(addr));
}
__device__ __forceinline__ void mma16816(float* d, const uint32_t* a, const uint32_t* b){
  asm volatile(
    "mma.sync.aligned.m16n8k16.row.col.f32.bf16.bf16.f32 "
    "{%0,%1,%2,%3}, {%4,%5,%6,%7}, {%8,%9}, {%0,%1,%2,%3};"
    : "+f"(d[0]), "+f"(d[1]), "+f"(d[2]), "+f"(d[3])
    : "r"(a[0]), "r"(a[1]), "r"(a[2]), "r"(a[3]), "r"(b[0]), "r"(b[1]));
}
__device__ __forceinline__ void cp16(uint32_t dst, const void* src, uint32_t sz){
  asm volatile("cp.async.cg.shared.global [%0], [%1], 16, %2;"
               :: "r"(dst), "l"(src), "r"(sz) : "memory");
}

// ---------------- K0a: split X into bf16 hi/lo, pixel-major transpose -------
__global__ void __launch_bounds__(256) k_xprep(const float* __restrict__ X){
  __shared__ float st[256][33];
  int b   = blockIdx.x >> 7;
  int hw0 = (blockIdx.x & 127) * 32;
  int tid = threadIdx.x;
  #pragma unroll 8
  for (int it = 0; it < 32; ++it){
    int idx = it*256 + tid;
    int ch = idx >> 5, w = idx & 31;
    st[ch][w] = X[((size_t)b*256 + ch)*4096 + hw0 + w];
  }
  __syncthreads();
  #pragma unroll 4
  for (int it = 0; it < 16; ++it){
    int idx = it*256 + tid;
    int w = idx >> 7, icp = idx & 127;
    float v0 = st[2*icp][w], v1 = st[2*icp + 1][w];
    uint32_t lo, hi = pack_hi(v0, v1, lo);
    size_t o = ((size_t)b*4096 + hw0 + w)*128 + icp;
    g_xhi[o] = hi; g_xlo[o] = lo;
  }
}

// ---------------- K0b: split + pre-swizzle weights per chunk ----------------
__global__ void __launch_bounds__(256) k_wprep(const float* __restrict__ W){
  int idx = blockIdx.x*256 + threadIdx.x;     // 36*4096 = 147456
  int chunk = idx >> 12;
  int rem = idx & 4095;
  int oc = rem >> 5, icp = rem & 31;
  int tap = chunk >> 2, icb = (chunk & 3) << 6;
  int ic = icb + 2*icp;
  float v0 = W[(size_t)(oc*256 + ic)*9 + tap];
  float v1 = W[(size_t)(oc*256 + ic + 1)*9 + tap];
  uint32_t lo, hi = pack_hi(v0, v1, lo);
  uint32_t off = ((uint32_t)(oc*128 + icp*4)) ^ (((uint32_t)(oc & 7)) << 4);
  g_wsplit[(chunk*32768u + off) >> 2]          = hi;
  g_wsplit[(chunk*32768u + 16384u + off) >> 2] = lo;
}

// ---------------- K1: conv as HMMA implicit GEMM, cp.async double-buffered --
// CTA: M=128 px (2 image rows) x N=128 oc, K=2304 in 36 chunks of 64.
// smem per stage 64KB: Ahi +0, Alo +16384, Bhi +32768, Blo +49152.
__global__ void __launch_bounds__(256) k_conv_mma(const float* __restrict__ cbp,
                                                  const float* __restrict__ bsc,
                                                  const float* __restrict__ bbi)
{
  extern __shared__ __align__(128) char sm[];
  __shared__ float s_prm[384];
  const int tid = threadIdx.x;
  const int wid = tid >> 5, lane = tid & 31;
  const int wm = wid & 3, wn = wid >> 2;
  const int b    = blockIdx.x >> 5;
  const int tile = blockIdx.x & 31;
  const int h0   = tile * 2;

  if (tid < 128){
    s_prm[tid]       = cbp[tid];
    s_prm[128 + tid] = bsc[tid];
    s_prm[256 + tid] = bbi[tid];
  }
  const uint32_t smb = smem_u32(sm);
  const int m = lane >> 3, r = lane & 7;
  const int fseg = tid & 7, fpr = tid >> 3;   // fill: 16B segment, row group

  // ldmatrix lane row/xor precompute
  int rowA[2], xrA[2];
  #pragma unroll
  for (int mt=0; mt<2; ++mt){
    rowA[mt] = wm*32 + mt*16 + (m & 1)*8 + r;
    xrA[mt]  = (rowA[mt] & 7) << 4;
  }
  const int colAhalf = (m >> 1) * 16;
  int rowB[4], xrB[4];
  #pragma unroll
  for (int ntp=0; ntp<4; ++ntp){
    rowB[ntp] = wn*64 + ntp*16 + (m >> 1)*8 + r;
    xrB[ntp]  = (rowB[ntp] & 7) << 4;
  }
  const int colBhalf = (m & 1) * 16;

  float acc[2][8][4];
  #pragma unroll
  for (int i=0;i<2;i++)
    #pragma unroll
    for (int j=0;j<8;j++)
      #pragma unroll
      for (int q=0;q<4;q++) acc[i][j][q] = 0.f;

  // ---- fill issue (cp.async) for chunk n into stage base sb ----
  auto fill = [&](int n, uint32_t sb){
    const int tap = n >> 2;
    const int icpg0 = (n & 3) << 5;
    const int dy = (tap / 3) * 3 - 3, dx = (tap % 3) * 3 - 3;
    #pragma unroll
    for (int it = 0; it < 4; ++it){
      int px = it*32 + fpr;
      int hh = h0 + (px >> 6) + dy;
      int ww = (px & 63) + dx;
      bool valid = ((unsigned)hh < 64u) && ((unsigned)ww < 64u);
      size_t gbase = (((size_t)b*4096) + (valid ? hh*64 + ww : 0))*128 + icpg0;
      uint32_t sz = valid ? 16u : 0u;
      uint32_t off = (uint32_t)(px*128) + (((uint32_t)(fseg*16)) ^ (((uint32_t)(px & 7)) << 4));
      cp16(smb + sb + off,          (const char*)(g_xhi + gbase) + fseg*16, sz);
      cp16(smb + sb + 16384 + off,  (const char*)(g_xlo + gbase) + fseg*16, sz);
    }
    const uint4* wsrc = (const uint4*)&g_wsplit[n * 8192];
    #pragma unroll
    for (int it = 0; it < 8; ++it){
      int idx = it*256 + tid;
      cp16(smb + sb + 32768 + idx*16, wsrc + idx, 16);
    }
    asm volatile("cp.async.commit_group;" ::: "memory");
  };

  fill(0, 0);
  for (int n = 0; n < 36; ++n){
    const uint32_t sb = (uint32_t)(n & 1) * 65536u;
    if (n < 35){
      fill(n + 1, (uint32_t)((n + 1) & 1) * 65536u);
      asm volatile("cp.async.wait_group 1;" ::: "memory");
    } else {
      asm volatile("cp.async.wait_group 0;" ::: "memory");
    }
    __syncthreads();

    // ---- MMA: warp tile 32(M) x 64(N), K=64 ----
    #pragma unroll
    for (int kk = 0; kk < 4; ++kk){
      uint32_t ah[2][4], al[2][4];
      const int colA = kk*32 + colAhalf;
      #pragma unroll
      for (int mt=0; mt<2; ++mt){
        uint32_t aaddr = smb + sb + rowA[mt]*128 + (colA ^ xrA[mt]);
        ldmx4(ah[mt], aaddr);
        ldmx4(al[mt], aaddr + 16384);
      }
      const int colB = kk*32 + colBhalf;
      #pragma unroll
      for (int ntp=0; ntp<4; ++ntp){
        uint32_t bh[4], bl[4];
        uint32_t baddr = smb + sb + 32768 + rowB[ntp]*128 + (colB ^ xrB[ntp]);
        ldmx4(bh, baddr);
        ldmx4(bl, baddr + 16384);
        #pragma unroll
        for (int mt=0; mt<2; ++mt){
          #pragma unroll
          for (int hf=0; hf<2; ++hf){
            float* d = acc[mt][ntp*2 + hf];
            mma16816(d, ah[mt], bh + hf*2);
            mma16816(d, ah[mt], bl + hf*2);
            mma16816(d, al[mt], bh + hf*2);
          }
        }
      }
    }
    __syncthreads();
  }

  // ---- epilogue: BN + ReLU + store ----
  const int g2 = lane >> 2, tig = lane & 3;
  float* outb = &g_conv[(size_t)b*128*4096 + h0*64];
  #pragma unroll
  for (int mt=0; mt<2; ++mt){
    int px0 = wm*32 + mt*16 + g2;
    #pragma unroll
    for (int nt=0; nt<8; ++nt){
      int oc0 = wn*64 + nt*8 + 2*tig;
      #pragma unroll
      for (int q=0; q<4; ++q){
        int px = px0 + (q >> 1)*8;
        int oc = oc0 + (q & 1);
        float v = (acc[mt][nt][q] + s_prm[oc]) * s_prm[128+oc] + s_prm[256+oc];
        outb[(size_t)oc*4096 + px] = fmaxf(v, 0.f);
      }
    }
  }
}

// ---------------- complex helpers ----------------
struct cpx { float x, y; };
__device__ __forceinline__ cpx mk(float a, float b){ cpx r; r.x=a; r.y=b; return r; }
__device__ __forceinline__ cpx cadd(cpx a, cpx b){ return mk(a.x+b.x, a.y+b.y); }
__device__ __forceinline__ cpx csub(cpx a, cpx b){ return mk(a.x-b.x, a.y-b.y); }
__device__ __forceinline__ cpx cmul(cpx a, cpx b){ return mk(a.x*b.x - a.y*b.y, a.x*b.y + a.y*b.x); }

template<int S>
__device__ __forceinline__ cpx mulJ(cpx a){
  return (S < 0) ? mk(a.y, -a.x) : mk(-a.y, a.x);
}
template<int S>
__device__ __forceinline__ cpx tw(int t, int N){
  t &= (N - 1);
  if (t > (N >> 1)) t -= N;
  float a = ((S < 0) ? -PI2F : PI2F) * (float)t / (float)N;
  float s, c;
  __sincosf(a, &s, &c);
  return mk(c, s);
}
template<int S>
__device__ __forceinline__ void dft8(cpx v[8]){
  const float r = 0.70710678118654752440f;
  cpx a0=cadd(v[0],v[4]), a1=csub(v[0],v[4]);
  cpx a2=cadd(v[2],v[6]), a3=csub(v[2],v[6]);
  cpx a4=cadd(v[1],v[5]), a5=csub(v[1],v[5]);
  cpx a6=cadd(v[3],v[7]), a7=csub(v[3],v[7]);
  cpx j3 = mulJ<S>(a3);
  cpx E0=cadd(a0,a2), E2=csub(a0,a2), E1=cadd(a1,j3), E3=csub(a1,j3);
  cpx j7 = mulJ<S>(a7);
  cpx O0=cadd(a4,a6), O2=csub(a4,a6), O1=cadd(a5,j7), O3=csub(a5,j7);
  cpx w1 = mk(r, (S<0)? -r : r);
  cpx w3 = mk(-r, (S<0)? -r : r);
  cpx t1 = cmul(O1, w1);
  cpx t2 = mulJ<S>(O2);
  cpx t3 = cmul(O3, w3);
  v[0]=cadd(E0,O0); v[4]=csub(E0,O0);
  v[1]=cadd(E1,t1); v[5]=csub(E1,t1);
  v[2]=cadd(E2,t2); v[6]=csub(E2,t2);
  v[3]=cadd(E3,t3); v[7]=csub(E3,t3);
}
template<int S>
__device__ void fft64(float* br, float* bi, int stride, int l){
  cpx v[8];
  #pragma unroll
  for (int j=0;j<8;j++){ int id=(l+8*j)*stride; v[j]=mk(br[id], bi[id]); }
  dft8<S>(v);
  #pragma unroll
  for (int k=1;k<8;k++) v[k] = cmul(v[k], tw<S>(l*k, 64));
  __syncthreads();
  #pragma unroll
  for (int k=0;k<8;k++){ int id=(l*8+k)*stride; br[id]=v[k].x; bi[id]=v[k].y; }
  __syncthreads();
  #pragma unroll
  for (int j=0;j<8;j++){ int id=(j*8+l)*stride; v[j]=mk(br[id], bi[id]); }
  dft8<S>(v);
  #pragma unroll
  for (int k=0;k<8;k++){ int id=(k*8+l)*stride; br[id]=v[k].x; bi[id]=v[k].y; }
  __syncthreads();
}

// ---------------- K2: forward fft2 over (h,w) + spectral row norms ----------
__global__ void __launch_bounds__(512) k_fft2(){
  __shared__ float sr[64][68], si[64][68];
  __shared__ float s_sum;
  int bc = blockIdx.x;
  int tid = threadIdx.x;
  if (tid==0) s_sum = 0.f;
  const float* src = &g_conv[bc*4096];
  for (int idx=tid; idx<4096; idx+=512){
    sr[idx>>6][idx&63] = src[idx];
    si[idx>>6][idx&63] = 0.f;
  }
  __syncthreads();
  int g = tid>>3, l = tid&7;
  fft64<-1>(&sr[0][g], &si[0][g], 68, l);
  fft64<-1>(&sr[g][0], &si[g][0], 1,  l);
  float part = 0.f;
  for (int idx=tid; idx<4096; idx+=512){
    float a = sr[idx>>6][idx&63], b2 = si[idx>>6][idx&63];
    g_f[bc*4096 + idx] = make_float2(a, b2);
    part += a*a + b2*b2;
  }
  #pragma unroll
  for (int s=16;s;s>>=1) part += __shfl_xor_sync(0xffffffffu, part, s);
  if ((tid&31)==0) atomicAdd(&s_sum, part);
  __syncthreads();
  if (tid==0) g_norm[bc] = sqrtf(s_sum);
}

// ---------------- K3: gram matrix + dual softmax ----------------
__global__ void __launch_bounds__(256) k_gram(const float* __restrict__ temp){
  __shared__ float2 sQ[16][129];
  int bh = blockIdx.x;
  int tid = threadIdx.x;
  int i = tid >> 4, jj = tid & 15;
  float ax=0.f, ay=0.f;
  for (int ch=0; ch<4096; ch+=128){
    for (int idx=tid; idx<2048; idx+=256)
      sQ[idx>>7][idx&127] = g_f[(bh*16 + (idx>>7))*4096 + ch + (idx&127)];
    __syncthreads();
    #pragma unroll 4
    for (int n=0;n<128;n++){
      float2 a = sQ[i][n], b = sQ[jj][n];
      ax = fmaf(a.x, b.x, ax); ax = fmaf(-a.y, b.y, ax);
      ay = fmaf(a.x, b.y, ay); ay = fmaf(a.y, b.x, ay);
    }
    __syncthreads();
  }
  float ni = fmaxf(g_norm[bh*16 + i],  1e-12f);
  float nj = fmaxf(g_norm[bh*16 + jj], 1e-12f);
  float sc = temp[bh & 7] / (ni*nj);
  float gr = ax*sc, gi = ay*sc;
  float mr = gr, mi = gi;
  #pragma unroll
  for (int m2=8;m2;m2>>=1){
    mr = fmaxf(mr, __shfl_xor_sync(0xffffffffu, mr, m2));
    mi = fmaxf(mi, __shfl_xor_sync(0xffffffffu, mi, m2));
  }
  float er = __expf(gr - mr), ei = __expf(gi - mi);
  float srn = er, sin_ = ei;
  #pragma unroll
  for (int m2=8;m2;m2>>=1){
    srn  += __shfl_xor_sync(0xffffffffu, srn, m2);
    sin_ += __shfl_xor_sync(0xffffffffu, sin_, m2);
  }
  g_attn[bh*256 + i*16 + jj] = make_float2(er/srn, ei/sin_);
}

// ---------------- K4: apply attention ----------------
__global__ void __launch_bounds__(512) k_apply(){
  __shared__ float2 sF[16][257];
  __shared__ float2 sA[256];
  int bh = blockIdx.x;
  int tid = threadIdx.x;
  if (tid < 256) sA[tid] = g_attn[bh*256 + tid];
  int nl = tid & 255;
  int ih = (tid >> 8) * 8;
  for (int ch=0; ch<4096; ch+=256){
    #pragma unroll
    for (int k=0;k<8;k++){
      int idx = tid + k*512;
      sF[idx>>8][idx&255] = g_f[(bh*16 + (idx>>8))*4096 + ch + (idx&255)];
    }
    __syncthreads();
    float2 acc[8];
    #pragma unroll
    for (int q=0;q<8;q++) acc[q] = make_float2(0.f, 0.f);
    #pragma unroll
    for (int j=0;j<16;j++){
      float2 fv = sF[j][nl];
      #pragma unroll
      for (int q=0;q<8;q++){
        float2 a = sA[(ih+q)*16 + j];
        acc[q].x = fmaf(a.x, fv.x, acc[q].x); acc[q].x = fmaf(-a.y, fv.y, acc[q].x);
        acc[q].y = fmaf(a.x, fv.y, acc[q].y); acc[q].y = fmaf(a.y, fv.x, acc[q].y);
      }
    }
    #pragma unroll
    for (int q=0;q<8;q++)
      g_outf[(bh*16 + ih + q)*4096 + ch + nl] = acc[q];
    __syncthreads();
  }
}

// ---------------- K5: in-place 4096-pt IFFT per row ----------
__global__ void __launch_bounds__(512) k_ifft4096(){
  __shared__ float sr[64][68], si[64][68];
  int row = blockIdx.x;
  int tid = threadIdx.x;
  float2* base = &g_outf[row*4096];
  for (int idx=tid; idx<4096; idx+=512){
    float2 v = base[idx];
    sr[idx>>6][idx&63] = v.x;
    si[idx>>6][idx&63] = v.y;
  }
  __syncthreads();
  int g = tid>>3, l = tid&7;
  fft64<1>(&sr[0][g], &si[0][g], 68, l);
  for (int idx=tid; idx<4096; idx+=512){
    int n2 = idx>>6, k1 = idx&63;
    cpx t = tw<1>(n2*k1, 4096);
    cpx v = mk(sr[n2][k1], si[n2][k1]);
    v = cmul(v, t);
    sr[n2][k1] = v.x; si[n2][k1] = v.y;
  }
  __syncthreads();
  fft64<1>(&sr[g][0], &si[g][0], 1, l);
  for (int idx=tid; idx<4096; idx+=512)
    base[idx] = make_float2(sr[idx&63][idx>>6], si[idx&63][idx>>6]);
}

// ---------------- K6: 16-pt IDFT over cp + abs + residual ----------
__global__ void __launch_bounds__(256) k_ifft16(const float* __restrict__ x,
                                                float* __restrict__ out){
  int t = blockIdx.x*256 + threadIdx.x;
  int bh = t >> 12;
  int n  = t & 4095;
  int b  = bh >> 3;
  int h  = bh & 7;
  float2 v[16];
  #pragma unroll
  for (int i=0;i<16;i++) v[i] = g_outf[(bh*16 + i)*4096 + n];
  #pragma unroll
  for (int ip=0; ip<16; ip++){
    float ax = 0.f, ay = 0.f;
    #pragma unroll
    for (int i=0;i<16;i++){
      float2 w2 = c_tw16[(i*ip) & 15];
      ax = fmaf(v[i].x, w2.x, ax); ax = fmaf(-v[i].y, w2.y, ax);
      ay = fmaf(v[i].x, w2.y, ay); ay = fmaf( v[i].y, w2.x, ay);
    }
    int c = h*16 + ip;
    int oi = (b*256 + c)*4096 + n;
    out[oi] = sqrtf(ax*ax + ay*ay) * (1.f/65536.f) + x[oi];
  }
}

// ---------------- K7: gating MLP, scales g_f in place ----------------
__global__ void __launch_bounds__(256) k_gate(const float* __restrict__ w1,
                                              const float* __restrict__ w1b,
                                              const float* __restrict__ bnws,
                                              const float* __restrict__ bnwb,
                                              const float* __restrict__ w2,
                                              const float* __restrict__ w2b)
{
  __shared__ float s_w1[8*128];
  __shared__ float s_w2[128*8];
  __shared__ float s_tb[8], s_ta[8];
  __shared__ float s_b2[128];
  int tid = threadIdx.x;
  for (int idx=tid; idx<1024; idx+=256){ s_w1[idx] = w1[idx]; s_w2[idx] = w2[idx]; }
  if (tid < 8){ float a = bnws[tid]; s_ta[tid] = a; s_tb[tid] = w1b[tid]*a + bnwb[tid]; }
  if (tid < 128) s_b2[tid] = w2b[tid];
  __syncthreads();

  int t = blockIdx.x*256 + tid;
  int b = t >> 12;
  int p = t & 4095;
  float2* fp = &g_f[(size_t)b*128*4096 + p];

  float acc[8];
  #pragma unroll
  for (int q=0;q<8;q++) acc[q] = 0.f;
  for (int c=0;c<128;c++){
    float r = fp[(size_t)c*4096].x;
    #pragma unroll
    for (int q=0;q<8;q++) acc[q] = fmaf(s_w1[q*128 + c], r, acc[q]);
  }
  float tq[8];
  #pragma unroll
  for (int q=0;q<8;q++) tq[q] = fmaxf(fmaf(acc[q], s_ta[q], s_tb[q]), 0.f);

  for (int c=0;c<128;c++){
    float s = s_b2[c];
    #pragma unroll
    for (int q=0;q<8;q++) s = fmaf(s_w2[c*8 + q], tq[q], s);
    float gate = 1.f / (1.f + __expf(-s));
    float2 fv = fp[(size_t)c*4096];
    fp[(size_t)c*4096] = make_float2(fv.x*gate, fv.y*gate);
  }
}

// ---------------- K8: spatial inverse fft2 of g*f + abs + residual ----------
__global__ void __launch_bounds__(512) k_ifft2sp(const float* __restrict__ x,
                                                 float* __restrict__ out){
  __shared__ float sr[64][68], si[64][68];
  int bc = blockIdx.x;
  int tid = threadIdx.x;
  const float2* base = &g_f[(size_t)bc*4096];
  for (int idx=tid; idx<4096; idx+=512){
    float2 v = base[idx];
    sr[idx>>6][idx&63] = v.x;
    si[idx>>6][idx&63] = v.y;
  }
  __syncthreads();
  int g = tid>>3, l = tid&7;
  fft64<1>(&sr[0][g], &si[0][g], 68, l);
  fft64<1>(&sr[g][0], &si[g][0], 1,  l);
  int b = bc >> 7, c = bc & 127;
  const float* xb = &x[((size_t)b*256 + 128 + c)*4096];
  float* ob = &out[((size_t)b*256 + 128 + c)*4096];
  for (int idx=tid; idx<4096; idx+=512){
    float a = sr[idx>>6][idx&63], b2 = si[idx>>6][idx&63];
    ob[idx] = sqrtf(a*a + b2*b2) * (1.f/4096.f) + xb[idx];
  }
}

// ---------------- launch ----------------
extern "C" void kernel_launch(void* const* d_in, const int* in_sizes, int n_in,
                              void* d_out, int out_size) {
  (void)in_sizes; (void)n_in; (void)out_size;
  const float* x     = (const float*)d_in[0];
  const float* c2w   = (const float*)d_in[1];
  const float* c2b   = (const float*)d_in[2];
  const float* bn2s  = (const float*)d_in[3];
  const float* bn2b  = (const float*)d_in[4];
  const float* temp  = (const float*)d_in[5];
  const float* w1w   = (const float*)d_in[6];
  const float* w1b   = (const float*)d_in[7];
  const float* bnws  = (const float*)d_in[8];
  const float* bnwb  = (const float*)d_in[9];
  const float* w2w   = (const float*)d_in[10];
  const float* w2b   = (const float*)d_in[11];
  float* out = (float*)d_out;

  const int SMEM_CONV = 2*65536;   // 128KB
  cudaFuncSetAttribute(k_conv_mma, cudaFuncAttributeMaxDynamicSharedMemorySize, SMEM_CONV);

  k_xprep<<<2048, 256>>>(x);
  k_wprep<<<576, 256>>>(c2w);
  k_conv_mma<<<512, 256, SMEM_CONV>>>(c2b, bn2s, bn2b);
  k_fft2<<<2048, 512>>>();
  k_gram<<<128, 256>>>(temp);
  k_apply<<<128, 512>>>();
  k_ifft4096<<<2048, 512>>>();
  k_ifft16<<<2048, 256>>>(x, out);
  k_gate<<<256, 256>>>(w1w, w1b, bnws, bnwb, w2w, w2b);
  k_ifft2sp<<<2048, 512>>>(x, out);
}

// round 6
// speedup vs baseline: 2.0600x; 1.0880x over previous
#include <cuda_runtime.h>
#include <cuda_bf16.h>
#include <math.h>
#include <stdint.h>

#define PI2F 6.28318530717958647692f

// ---------------- scratch (device globals; no allocation) ----------------
static __device__ float  g_conv[16*128*4096];      // conv2+BN+ReLU output
static __device__ float2 g_f   [16*128*4096];      // fft2 spectrum (later overwritten by g*f)
static __device__ float  g_norm[16*128];           // per-(b,c) spectral L2 norm
static __device__ float2 g_attn[16*8*256];         // softmaxed attention (b,h,16,16)
static __device__ float2 g_outf[16*128*4096];      // attention-applied spectrum / ifft scratch
static __device__ uint32_t g_xhi[16*4096*128];     // X split hi, pixel-major: [b][hw][icp]
static __device__ uint32_t g_xlo[16*4096*128];     // X split lo, pixel-major
static __device__ uint32_t g_wsplit[36*8192];      // weight chunks, pre-swizzled hi/lo planes
static __device__ float2 g_gpart[8*128*256];       // partial gram sums [seg][bh][256]

// 16-pt inverse twiddles e^{+2*pi*i*t/16}
__constant__ float2 c_tw16[16] = {
  { 1.00000000f,  0.00000000f}, { 0.92387953f,  0.38268343f},
  { 0.70710678f,  0.70710678f}, { 0.38268343f,  0.92387953f},
  { 0.00000000f,  1.00000000f}, {-0.38268343f,  0.92387953f},
  {-0.70710678f,  0.70710678f}, {-0.92387953f,  0.38268343f},
  {-1.00000000f,  0.00000000f}, {-0.92387953f, -0.38268343f},
  {-0.70710678f, -0.70710678f}, {-0.38268343f, -0.92387953f},
  { 0.00000000f, -1.00000000f}, { 0.38268343f, -0.92387953f},
  { 0.70710678f, -0.70710678f}, { 0.92387953f, -0.38268343f}
};

// ================= helpers =================
__device__ __forceinline__ uint32_t smem_u32(const void* p){
  uint32_t a;
  asm("{ .reg .u64 t; cvta.to.shared.u64 t, %1; cvt.u32.u64 %0, t; }" : "=r"(a) : "l"(p));
  return a;
}
__device__ __forceinline__ uint32_t pack_hi(float v0, float v1, uint32_t& lo){
  __nv_bfloat16 a0 = __float2bfloat16_rn(v0), a1 = __float2bfloat16_rn(v1);
  __nv_bfloat16 l0 = __float2bfloat16_rn(v0 - __bfloat162float(a0));
  __nv_bfloat16 l1 = __float2bfloat16_rn(v1 - __bfloat162float(a1));
  lo = (uint32_t)__bfloat16_as_ushort(l0) | ((uint32_t)__bfloat16_as_ushort(l1) << 16);
  return (uint32_t)__bfloat16_as_ushort(a0) | ((uint32_t)__bfloat16_as_ushort(a1) << 16);
}
__device__ __forceinline__ void ldmx4(uint32_t* d, uint32_t addr){
  asm volatile("ldmatrix.sync.aligned.m8n8.x4.shared.b16 {%0,%1,%2,%3}, [%4];"
               : "=r"(d[0]), "=r"(d[1]), "=r"(d[2]), "=r"(d[3]) : "r"(addr));
}
__device__ __forceinline__ void mma16816(float* d, const uint32_t* a, const uint32_t* b){
  asm volatile(
    "mma.sync.aligned.m16n8k16.row.col.f32.bf16.bf16.f32 "
    "{%0,%1,%2,%3}, {%4,%5,%6,%7}, {%8,%9}, {%0,%1,%2,%3};"
    : "+f"(d[0]), "+f"(d[1]), "+f"(d[2]), "+f"(d[3])
    : "r"(a[0]), "r"(a[1]), "r"(a[2]), "r"(a[3]), "r"(b[0]), "r"(b[1]));
}
__device__ __forceinline__ void cp16(uint32_t dst, const void* src, uint32_t sz){
  asm volatile("cp.async.cg.shared.global [%0], [%1], 16, %2;"
               :: "r"(dst), "l"(src), "r"(sz) : "memory");
}

// ---------------- K0a: split X into bf16 hi/lo, pixel-major transpose -------
__global__ void __launch_bounds__(256) k_xprep(const float* __restrict__ X){
  __shared__ float st[256][33];
  int b   = blockIdx.x >> 7;
  int hw0 = (blockIdx.x & 127) * 32;
  int tid = threadIdx.x;
  #pragma unroll 8
  for (int it = 0; it < 32; ++it){
    int idx = it*256 + tid;
    int ch = idx >> 5, w = idx & 31;
    st[ch][w] = X[((size_t)b*256 + ch)*4096 + hw0 + w];
  }
  __syncthreads();
  #pragma unroll 4
  for (int it = 0; it < 16; ++it){
    int idx = it*256 + tid;
    int w = idx >> 7, icp = idx & 127;
    float v0 = st[2*icp][w], v1 = st[2*icp + 1][w];
    uint32_t lo, hi = pack_hi(v0, v1, lo);
    size_t o = ((size_t)b*4096 + hw0 + w)*128 + icp;
    g_xhi[o] = hi; g_xlo[o] = lo;
  }
}

// ---------------- K0b: split + pre-swizzle weights per chunk ----------------
__global__ void __launch_bounds__(256) k_wprep(const float* __restrict__ W){
  int idx = blockIdx.x*256 + threadIdx.x;     // 36*4096 = 147456
  int chunk = idx >> 12;
  int rem = idx & 4095;
  int oc = rem >> 5, icp = rem & 31;
  int tap = chunk >> 2, icb = (chunk & 3) << 6;
  int ic = icb + 2*icp;
  float v0 = W[(size_t)(oc*256 + ic)*9 + tap];
  float v1 = W[(size_t)(oc*256 + ic + 1)*9 + tap];
  uint32_t lo, hi = pack_hi(v0, v1, lo);
  uint32_t off = ((uint32_t)(oc*128 + icp*4)) ^ (((uint32_t)(oc & 7)) << 4);
  g_wsplit[(chunk*32768u + off) >> 2]          = hi;
  g_wsplit[(chunk*32768u + 16384u + off) >> 2] = lo;
}

// ---------------- K1: conv as HMMA implicit GEMM, cp.async double-buffered --
__global__ void __launch_bounds__(256) k_conv_mma(const float* __restrict__ cbp,
                                                  const float* __restrict__ bsc,
                                                  const float* __restrict__ bbi)
{
  extern __shared__ __align__(128) char sm[];
  __shared__ float s_prm[384];
  const int tid = threadIdx.x;
  const int wid = tid >> 5, lane = tid & 31;
  const int wm = wid & 3, wn = wid >> 2;
  const int b    = blockIdx.x >> 5;
  const int tile = blockIdx.x & 31;
  const int h0   = tile * 2;

  if (tid < 128){
    s_prm[tid]       = cbp[tid];
    s_prm[128 + tid] = bsc[tid];
    s_prm[256 + tid] = bbi[tid];
  }
  const uint32_t smb = smem_u32(sm);
  const int m = lane >> 3, r = lane & 7;
  const int fseg = tid & 7, fpr = tid >> 3;

  int rowA[2], xrA[2];
  #pragma unroll
  for (int mt=0; mt<2; ++mt){
    rowA[mt] = wm*32 + mt*16 + (m & 1)*8 + r;
    xrA[mt]  = (rowA[mt] & 7) << 4;
  }
  const int colAhalf = (m >> 1) * 16;
  int rowB[4], xrB[4];
  #pragma unroll
  for (int ntp=0; ntp<4; ++ntp){
    rowB[ntp] = wn*64 + ntp*16 + (m >> 1)*8 + r;
    xrB[ntp]  = (rowB[ntp] & 7) << 4;
  }
  const int colBhalf = (m & 1) * 16;

  float acc[2][8][4];
  #pragma unroll
  for (int i=0;i<2;i++)
    #pragma unroll
    for (int j=0;j<8;j++)
      #pragma unroll
      for (int q=0;q<4;q++) acc[i][j][q] = 0.f;

  auto fill = [&](int n, uint32_t sb){
    const int tap = n >> 2;
    const int icpg0 = (n & 3) << 5;
    const int dy = (tap / 3) * 3 - 3, dx = (tap % 3) * 3 - 3;
    #pragma unroll
    for (int it = 0; it < 4; ++it){
      int px = it*32 + fpr;
      int hh = h0 + (px >> 6) + dy;
      int ww = (px & 63) + dx;
      bool valid = ((unsigned)hh < 64u) && ((unsigned)ww < 64u);
      size_t gbase = (((size_t)b*4096) + (valid ? hh*64 + ww : 0))*128 + icpg0;
      uint32_t sz = valid ? 16u : 0u;
      uint32_t off = (uint32_t)(px*128) + (((uint32_t)(fseg*16)) ^ (((uint32_t)(px & 7)) << 4));
      cp16(smb + sb + off,          (const char*)(g_xhi + gbase) + fseg*16, sz);
      cp16(smb + sb + 16384 + off,  (const char*)(g_xlo + gbase) + fseg*16, sz);
    }
    const uint4* wsrc = (const uint4*)&g_wsplit[n * 8192];
    #pragma unroll
    for (int it = 0; it < 8; ++it){
      int idx = it*256 + tid;
      cp16(smb + sb + 32768 + idx*16, wsrc + idx, 16);
    }
    asm volatile("cp.async.commit_group;" ::: "memory");
  };

  fill(0, 0);
  for (int n = 0; n < 36; ++n){
    const uint32_t sb = (uint32_t)(n & 1) * 65536u;
    if (n < 35){
      fill(n + 1, (uint32_t)((n + 1) & 1) * 65536u);
      asm volatile("cp.async.wait_group 1;" ::: "memory");
    } else {
      asm volatile("cp.async.wait_group 0;" ::: "memory");
    }
    __syncthreads();

    #pragma unroll
    for (int kk = 0; kk < 4; ++kk){
      uint32_t ah[2][4], al[2][4];
      const int colA = kk*32 + colAhalf;
      #pragma unroll
      for (int mt=0; mt<2; ++mt){
        uint32_t aaddr = smb + sb + rowA[mt]*128 + (colA ^ xrA[mt]);
        ldmx4(ah[mt], aaddr);
        ldmx4(al[mt], aaddr + 16384);
      }
      const int colB = kk*32 + colBhalf;
      #pragma unroll
      for (int ntp=0; ntp<4; ++ntp){
        uint32_t bh[4], bl[4];
        uint32_t baddr = smb + sb + 32768 + rowB[ntp]*128 + (colB ^ xrB[ntp]);
        ldmx4(bh, baddr);
        ldmx4(bl, baddr + 16384);
        #pragma unroll
        for (int mt=0; mt<2; ++mt){
          #pragma unroll
          for (int hf=0; hf<2; ++hf){
            float* d = acc[mt][ntp*2 + hf];
            mma16816(d, ah[mt], bh + hf*2);
            mma16816(d, ah[mt], bl + hf*2);
            mma16816(d, al[mt], bh + hf*2);
          }
        }
      }
    }
    __syncthreads();
  }

  const int g2 = lane >> 2, tig = lane & 3;
  float* outb = &g_conv[(size_t)b*128*4096 + h0*64];
  #pragma unroll
  for (int mt=0; mt<2; ++mt){
    int px0 = wm*32 + mt*16 + g2;
    #pragma unroll
    for (int nt=0; nt<8; ++nt){
      int oc0 = wn*64 + nt*8 + 2*tig;
      #pragma unroll
      for (int q=0; q<4; ++q){
        int px = px0 + (q >> 1)*8;
        int oc = oc0 + (q & 1);
        float v = (acc[mt][nt][q] + s_prm[oc]) * s_prm[128+oc] + s_prm[256+oc];
        outb[(size_t)oc*4096 + px] = fmaxf(v, 0.f);
      }
    }
  }
}

// ---------------- complex helpers ----------------
struct cpx { float x, y; };
__device__ __forceinline__ cpx mk(float a, float b){ cpx r; r.x=a; r.y=b; return r; }
__device__ __forceinline__ cpx cadd(cpx a, cpx b){ return mk(a.x+b.x, a.y+b.y); }
__device__ __forceinline__ cpx csub(cpx a, cpx b){ return mk(a.x-b.x, a.y-b.y); }
__device__ __forceinline__ cpx cmul(cpx a, cpx b){ return mk(a.x*b.x - a.y*b.y, a.x*b.y + a.y*b.x); }

template<int S>
__device__ __forceinline__ cpx mulJ(cpx a){
  return (S < 0) ? mk(a.y, -a.x) : mk(-a.y, a.x);
}
template<int S>
__device__ __forceinline__ cpx tw(int t, int N){
  t &= (N - 1);
  if (t > (N >> 1)) t -= N;
  float a = ((S < 0) ? -PI2F : PI2F) * (float)t / (float)N;
  float s, c;
  __sincosf(a, &s, &c);
  return mk(c, s);
}
template<int S>
__device__ __forceinline__ void dft8(cpx v[8]){
  const float r = 0.70710678118654752440f;
  cpx a0=cadd(v[0],v[4]), a1=csub(v[0],v[4]);
  cpx a2=cadd(v[2],v[6]), a3=csub(v[2],v[6]);
  cpx a4=cadd(v[1],v[5]), a5=csub(v[1],v[5]);
  cpx a6=cadd(v[3],v[7]), a7=csub(v[3],v[7]);
  cpx j3 = mulJ<S>(a3);
  cpx E0=cadd(a0,a2), E2=csub(a0,a2), E1=cadd(a1,j3), E3=csub(a1,j3);
  cpx j7 = mulJ<S>(a7);
  cpx O0=cadd(a4,a6), O2=csub(a4,a6), O1=cadd(a5,j7), O3=csub(a5,j7);
  cpx w1 = mk(r, (S<0)? -r : r);
  cpx w3 = mk(-r, (S<0)? -r : r);
  cpx t1 = cmul(O1, w1);
  cpx t2 = mulJ<S>(O2);
  cpx t3 = cmul(O3, w3);
  v[0]=cadd(E0,O0); v[4]=csub(E0,O0);
  v[1]=cadd(E1,t1); v[5]=csub(E1,t1);
  v[2]=cadd(E2,t2); v[6]=csub(E2,t2);
  v[3]=cadd(E3,t3); v[7]=csub(E3,t3);
}
// 64-pt DFT by an 8-thread group; exchanges are group-local -> __syncwarp.
// Ends with __syncthreads (cross-group handoff for the caller).
template<int S>
__device__ void fft64(float* br, float* bi, int stride, int l){
  cpx v[8];
  #pragma unroll
  for (int j=0;j<8;j++){ int id=(l+8*j)*stride; v[j]=mk(br[id], bi[id]); }
  dft8<S>(v);
  #pragma unroll
  for (int k=1;k<8;k++) v[k] = cmul(v[k], tw<S>(l*k, 64));
  __syncwarp();
  #pragma unroll
  for (int k=0;k<8;k++){ int id=(l*8+k)*stride; br[id]=v[k].x; bi[id]=v[k].y; }
  __syncwarp();
  #pragma unroll
  for (int j=0;j<8;j++){ int id=(j*8+l)*stride; v[j]=mk(br[id], bi[id]); }
  dft8<S>(v);
  #pragma unroll
  for (int k=0;k<8;k++){ int id=(k*8+l)*stride; br[id]=v[k].x; bi[id]=v[k].y; }
  __syncthreads();
}

// ---------------- K2: forward fft2 over (h,w) + spectral row norms ----------
__global__ void __launch_bounds__(512) k_fft2(){
  __shared__ float sr[64][68], si[64][68];
  __shared__ float s_sum;
  int bc = blockIdx.x;
  int tid = threadIdx.x;
  if (tid==0) s_sum = 0.f;
  const float* src = &g_conv[bc*4096];
  for (int idx=tid; idx<4096; idx+=512){
    sr[idx>>6][idx&63] = src[idx];
    si[idx>>6][idx&63] = 0.f;
  }
  __syncthreads();
  int g = tid>>3, l = tid&7;
  fft64<-1>(&sr[0][g], &si[0][g], 68, l);
  fft64<-1>(&sr[g][0], &si[g][0], 1,  l);
  float part = 0.f;
  for (int idx=tid; idx<4096; idx+=512){
    float a = sr[idx>>6][idx&63], b2 = si[idx>>6][idx&63];
    g_f[bc*4096 + idx] = make_float2(a, b2);
    part += a*a + b2*b2;
  }
  #pragma unroll
  for (int s=16;s;s>>=1) part += __shfl_xor_sync(0xffffffffu, part, s);
  if ((tid&31)==0) atomicAdd(&s_sum, part);
  __syncthreads();
  if (tid==0) g_norm[bc] = sqrtf(s_sum);
}

// ---------------- K3a: partial gram sums (deterministic two-phase) ----------
__global__ void __launch_bounds__(256) k_gram_part(){
  __shared__ float2 sQ[16][129];
  int bh  = blockIdx.x >> 3;
  int seg = blockIdx.x & 7;
  int tid = threadIdx.x;
  int i = tid >> 4, jj = tid & 15;
  float ax=0.f, ay=0.f;
  int ch0 = seg * 512;
  for (int ch = ch0; ch < ch0 + 512; ch += 128){
    for (int idx=tid; idx<2048; idx+=256)
      sQ[idx>>7][idx&127] = g_f[(bh*16 + (idx>>7))*4096 + ch + (idx&127)];
    __syncthreads();
    #pragma unroll 4
    for (int n=0;n<128;n++){
      float2 a = sQ[i][n], b = sQ[jj][n];
      ax = fmaf(a.x, b.x, ax); ax = fmaf(-a.y, b.y, ax);
      ay = fmaf(a.x, b.y, ay); ay = fmaf(a.y, b.x, ay);
    }
    __syncthreads();
  }
  g_gpart[(seg*128 + bh)*256 + tid] = make_float2(ax, ay);
}

// ---------------- K3b: reduce partials + normalize + dual softmax -----------
__global__ void __launch_bounds__(256) k_gram_fin(const float* __restrict__ temp){
  int bh = blockIdx.x;
  int tid = threadIdx.x;
  int i = tid >> 4, jj = tid & 15;
  float ax=0.f, ay=0.f;
  #pragma unroll
  for (int s=0;s<8;s++){
    float2 p = g_gpart[(s*128 + bh)*256 + tid];
    ax += p.x; ay += p.y;
  }
  float ni = fmaxf(g_norm[bh*16 + i],  1e-12f);
  float nj = fmaxf(g_norm[bh*16 + jj], 1e-12f);
  float sc = temp[bh & 7] / (ni*nj);
  float gr = ax*sc, gi = ay*sc;
  float mr = gr, mi = gi;
  #pragma unroll
  for (int m2=8;m2;m2>>=1){
    mr = fmaxf(mr, __shfl_xor_sync(0xffffffffu, mr, m2));
    mi = fmaxf(mi, __shfl_xor_sync(0xffffffffu, mi, m2));
  }
  float er = __expf(gr - mr), ei = __expf(gi - mi);
  float srn = er, sin_ = ei;
  #pragma unroll
  for (int m2=8;m2;m2>>=1){
    srn  += __shfl_xor_sync(0xffffffffu, srn, m2);
    sin_ += __shfl_xor_sync(0xffffffffu, sin_, m2);
  }
  g_attn[bh*256 + tid] = make_float2(er/srn, ei/sin_);
}

// ---------------- K4: apply attention (4-way ch split) ----------------
__global__ void __launch_bounds__(512) k_apply(){
  __shared__ float2 sF[16][257];
  __shared__ float2 sA[256];
  int bh = blockIdx.x >> 2;
  int cq = blockIdx.x & 3;
  int tid = threadIdx.x;
  if (tid < 256) sA[tid] = g_attn[bh*256 + tid];
  int nl = tid & 255;
  int ih = (tid >> 8) * 8;
  int ch0 = cq * 1024;
  for (int ch=ch0; ch<ch0+1024; ch+=256){
    #pragma unroll
    for (int k=0;k<8;k++){
      int idx = tid + k*512;
      sF[idx>>8][idx&255] = g_f[(bh*16 + (idx>>8))*4096 + ch + (idx&255)];
    }
    __syncthreads();
    float2 acc[8];
    #pragma unroll
    for (int q=0;q<8;q++) acc[q] = make_float2(0.f, 0.f);
    #pragma unroll
    for (int j=0;j<16;j++){
      float2 fv = sF[j][nl];
      #pragma unroll
      for (int q=0;q<8;q++){
        float2 a = sA[(ih+q)*16 + j];
        acc[q].x = fmaf(a.x, fv.x, acc[q].x); acc[q].x = fmaf(-a.y, fv.y, acc[q].x);
        acc[q].y = fmaf(a.x, fv.y, acc[q].y); acc[q].y = fmaf(a.y, fv.x, acc[q].y);
      }
    }
    #pragma unroll
    for (int q=0;q<8;q++)
      g_outf[(bh*16 + ih + q)*4096 + ch + nl] = acc[q];
    __syncthreads();
  }
}

// ---------------- K5: in-place 4096-pt IFFT per row ----------
__global__ void __launch_bounds__(512) k_ifft4096(){
  __shared__ float sr[64][68], si[64][68];
  int row = blockIdx.x;
  int tid = threadIdx.x;
  float2* base = &g_outf[row*4096];
  for (int idx=tid; idx<4096; idx+=512){
    float2 v = base[idx];
    sr[idx>>6][idx&63] = v.x;
    si[idx>>6][idx&63] = v.y;
  }
  __syncthreads();
  int g = tid>>3, l = tid&7;
  fft64<1>(&sr[0][g], &si[0][g], 68, l);
  for (int idx=tid; idx<4096; idx+=512){
    int n2 = idx>>6, k1 = idx&63;
    cpx t = tw<1>(n2*k1, 4096);
    cpx v = mk(sr[n2][k1], si[n2][k1]);
    v = cmul(v, t);
    sr[n2][k1] = v.x; si[n2][k1] = v.y;
  }
  __syncthreads();
  fft64<1>(&sr[g][0], &si[g][0], 1, l);
  for (int idx=tid; idx<4096; idx+=512)
    base[idx] = make_float2(sr[idx&63][idx>>6], si[idx&63][idx>>6]);
}

// ---------------- K6: 16-pt IDFT over cp + abs + residual ----------
__global__ void __launch_bounds__(256) k_ifft16(const float* __restrict__ x,
                                                float* __restrict__ out){
  int t = blockIdx.x*256 + threadIdx.x;
  int bh = t >> 12;
  int n  = t & 4095;
  int b  = bh >> 3;
  int h  = bh & 7;
  float2 v[16];
  #pragma unroll
  for (int i=0;i<16;i++) v[i] = g_outf[(bh*16 + i)*4096 + n];
  #pragma unroll
  for (int ip=0; ip<16; ip++){
    float ax = 0.f, ay = 0.f;
    #pragma unroll
    for (int i=0;i<16;i++){
      float2 w2 = c_tw16[(i*ip) & 15];
      ax = fmaf(v[i].x, w2.x, ax); ax = fmaf(-v[i].y, w2.y, ax);
      ay = fmaf(v[i].x, w2.y, ay); ay = fmaf( v[i].y, w2.x, ay);
    }
    int c = h*16 + ip;
    int oi = (b*256 + c)*4096 + n;
    out[oi] = sqrtf(ax*ax + ay*ay) * (1.f/65536.f) + x[oi];
  }
}

// ---------------- K7: gating MLP, scales g_f in place ----------------
__global__ void __launch_bounds__(256) k_gate(const float* __restrict__ w1,
                                              const float* __restrict__ w1b,
                                              const float* __restrict__ bnws,
                                              const float* __restrict__ bnwb,
                                              const float* __restrict__ w2,
                                              const float* __restrict__ w2b)
{
  __shared__ float s_w1[8*128];
  __shared__ float s_w2[128*8];
  __shared__ float s_tb[8], s_ta[8];
  __shared__ float s_b2[128];
  int tid = threadIdx.x;
  for (int idx=tid; idx<1024; idx+=256){ s_w1[idx] = w1[idx]; s_w2[idx] = w2[idx]; }
  if (tid < 8){ float a = bnws[tid]; s_ta[tid] = a; s_tb[tid] = w1b[tid]*a + bnwb[tid]; }
  if (tid < 128) s_b2[tid] = w2b[tid];
  __syncthreads();

  int t = blockIdx.x*256 + tid;
  int b = t >> 12;
  int p = t & 4095;
  float2* fp = &g_f[(size_t)b*128*4096 + p];

  float acc[8];
  #pragma unroll
  for (int q=0;q<8;q++) acc[q] = 0.f;
  for (int c=0;c<128;c++){
    float r = fp[(size_t)c*4096].x;
    #pragma unroll
    for (int q=0;q<8;q++) acc[q] = fmaf(s_w1[q*128 + c], r, acc[q]);
  }
  float tq[8];
  #pragma unroll
  for (int q=0;q<8;q++) tq[q] = fmaxf(fmaf(acc[q], s_ta[q], s_tb[q]), 0.f);

  for (int c=0;c<128;c++){
    float s = s_b2[c];
    #pragma unroll
    for (int q=0;q<8;q++) s = fmaf(s_w2[c*8 + q], tq[q], s);
    float gate = 1.f / (1.f + __expf(-s));
    float2 fv = fp[(size_t)c*4096];
    fp[(size_t)c*4096] = make_float2(fv.x*gate, fv.y*gate);
  }
}

// ---------------- K8: spatial inverse fft2 of g*f + abs + residual ----------
__global__ void __launch_bounds__(512) k_ifft2sp(const float* __restrict__ x,
                                                 float* __restrict__ out){
  __shared__ float sr[64][68], si[64][68];
  int bc = blockIdx.x;
  int tid = threadIdx.x;
  const float2* base = &g_f[(size_t)bc*4096];
  for (int idx=tid; idx<4096; idx+=512){
    float2 v = base[idx];
    sr[idx>>6][idx&63] = v.x;
    si[idx>>6][idx&63] = v.y;
  }
  __syncthreads();
  int g = tid>>3, l = tid&7;
  fft64<1>(&sr[0][g], &si[0][g], 68, l);
  fft64<1>(&sr[g][0], &si[g][0], 1,  l);
  int b = bc >> 7, c = bc & 127;
  const float* xb = &x[((size_t)b*256 + 128 + c)*4096];
  float* ob = &out[((size_t)b*256 + 128 + c)*4096];
  for (int idx=tid; idx<4096; idx+=512){
    float a = sr[idx>>6][idx&63], b2 = si[idx>>6][idx&63];
    ob[idx] = sqrtf(a*a + b2*b2) * (1.f/4096.f) + xb[idx];
  }
}

// ---------------- launch ----------------
extern "C" void kernel_launch(void* const* d_in, const int* in_sizes, int n_in,
                              void* d_out, int out_size) {
  (void)in_sizes; (void)n_in; (void)out_size;
  const float* x     = (const float*)d_in[0];
  const float* c2w   = (const float*)d_in[1];
  const float* c2b   = (const float*)d_in[2];
  const float* bn2s  = (const float*)d_in[3];
  const float* bn2b  = (const float*)d_in[4];
  const float* temp  = (const float*)d_in[5];
  const float* w1w   = (const float*)d_in[6];
  const float* w1b   = (const float*)d_in[7];
  const float* bnws  = (const float*)d_in[8];
  const float* bnwb  = (const float*)d_in[9];
  const float* w2w   = (const float*)d_in[10];
  const float* w2b   = (const float*)d_in[11];
  float* out = (float*)d_out;

  const int SMEM_CONV = 2*65536;   // 128KB
  cudaFuncSetAttribute(k_conv_mma, cudaFuncAttributeMaxDynamicSharedMemorySize, SMEM_CONV);

  k_xprep<<<2048, 256>>>(x);
  k_wprep<<<576, 256>>>(c2w);
  k_conv_mma<<<512, 256, SMEM_CONV>>>(c2b, bn2s, bn2b);
  k_fft2<<<2048, 512>>>();
  k_gram_part<<<1024, 256>>>();
  k_gram_fin<<<128, 256>>>(temp);
  k_apply<<<512, 512>>>();
  k_ifft4096<<<2048, 512>>>();
  k_ifft16<<<2048, 256>>>(x, out);
  k_gate<<<256, 256>>>(w1w, w1b, bnws, bnwb, w2w, w2b);
  k_ifft2sp<<<2048, 512>>>(x, out);
}